// round 12
// baseline (speedup 1.0000x reference)
#include <cuda_runtime.h>
#include <cuda_bf16.h>
#include <cuda_fp16.h>
#include <math.h>
#include <stdint.h>

#define SDIM 768
#define CCH  128
#define NTOK (SDIM*SDIM)        // 589824 tokens
#define SELEM 75497472          // 128 * 589824
#define NSM   148

// Scratch: a, b, tri all fp16
__device__ __half g_ahi[SELEM];
__device__ __half g_bhi[SELEM];
__device__ __half g_tri16[SELEM];

// Prepped fp16 weights:
// g_wcI: 4 groups x 128 rows x 128 k; group g row 2r = wgi col(64g+r), row 2r+1 = wpi col(64g+r)
__device__ __half g_wcI[4*128*128];
__device__ __half g_wgo16[128*128];   // wgo^T [n][k]
__device__ __half g_wpo16[128*128];   // wpo^T [co][h]

__device__ __forceinline__ float sigmoidf_(float v) {
    return 1.f / (1.f + __expf(-v));
}
__device__ __forceinline__ uint32_t smem_u32(const void* p) {
    uint32_t a;
    asm("{ .reg .u64 t; cvta.to.shared.u64 t, %1; cvt.u32.u64 %0, t; }"
        : "=r"(a) : "l"(p));
    return a;
}
#define CP_ASYNC16(d, s)  asm volatile("cp.async.cg.shared.global [%0], [%1], 16;" :: "r"(d), "l"(s))
#define CP_COMMIT()       asm volatile("cp.async.commit_group;" ::: "memory")
#define CP_WAIT0()        asm volatile("cp.async.wait_group 0;" ::: "memory")
#define CP_WAIT2()        asm volatile("cp.async.wait_group 2;" ::: "memory")

__device__ __forceinline__ void ldsm4(uint32_t* r, uint32_t addr) {
    asm volatile("ldmatrix.sync.aligned.m8n8.x4.shared.b16 {%0,%1,%2,%3}, [%4];"
        : "=r"(r[0]), "=r"(r[1]), "=r"(r[2]), "=r"(r[3]) : "r"(addr));
}
__device__ __forceinline__ void mma16816h(float* d, const uint32_t* a, const uint32_t* b) {
    asm volatile("mma.sync.aligned.m16n8k16.row.col.f32.f16.f16.f32 "
        "{%0,%1,%2,%3}, {%4,%5,%6,%7}, {%8,%9}, {%0,%1,%2,%3};"
        : "+f"(d[0]), "+f"(d[1]), "+f"(d[2]), "+f"(d[3])
        : "r"(a[0]), "r"(a[1]), "r"(a[2]), "r"(a[3]), "r"(b[0]), "r"(b[1]));
}

// ---------------------------------------------------------------------------
// Kernel 0: weight prep.
// ---------------------------------------------------------------------------
__global__ void __launch_bounds__(256) prep_w_kernel(
    const float* __restrict__ wgi, const float* __restrict__ wpi,
    const float* __restrict__ wgo, const float* __restrict__ wpo)
{
    int idx = blockIdx.x*256 + threadIdx.x;   // 0..65535
    {
        int g = idx >> 14, rem = idx & 16383;
        int row = rem >> 7, k = rem & 127;
        int col = g*64 + (row >> 1);
        float v = (row & 1) ? wpi[k*256 + col] : wgi[k*256 + col];
        g_wcI[idx] = __float2half_rn(v);
    }
    if (idx < 16384) {
        int n = idx >> 7, k = idx & 127;
        g_wgo16[idx] = __float2half_rn(wgo[k*128 + n]);
        g_wpo16[idx] = __float2half_rn(wpo[k*128 + n]);
    }
}

// ---------------------------------------------------------------------------
// Kernel 1: proj6 — persistent; grid (148,2), 2 CTAs/SM.
// job0: a chunks {0,1} (masked); job1: b chunks {2,3}. B resident per CTA.
// ---------------------------------------------------------------------------
#define PROW   272
#define PTILE  (128*PROW)         // 34816
#define ATILE  (64*PROW)          // 17408
#define P6_A    0
#define P6_B    ATILE                      // 17408
#define P6_TP   (P6_B + 2*PTILE)           // 87040
#define P6_SMEM (P6_TP + 64*68*4)          // 104448
#define NP6     (NTOK/64)                  // 9216

__global__ void __launch_bounds__(256, 2) proj6_kernel(
    const float* __restrict__ x, const float* __restrict__ mask,
    const float* __restrict__ nw, const float* __restrict__ nb)
{
    extern __shared__ char sm[];
    const uint32_t base = smem_u32(sm);
    const int tid = threadIdx.x;
    const int bid = blockIdx.x;
    const int job = blockIdx.y;           // 0 = a, 1 = b

    const int wid  = tid >> 5;
    const int lane = tid & 31;
    const int m_base = (wid >> 2) * 32;
    const int n_base = (wid & 3) * 32;
    const int a_row  = lane & 15;
    const int a_half = lane >> 4;
    const int b_quad = lane >> 3;
    const int b_row  = (b_quad >> 1)*8 + (lane & 7);
    const int b_half = b_quad & 1;

    // --- load this job's 2 B chunks once ---
    const __half* csrc0 = g_wcI + (size_t)(2*job)   * 16384;
    const __half* csrc1 = g_wcI + (size_t)(2*job+1) * 16384;
    {
        const __half* srcs[2] = { csrc0, csrc1 };
        for (int cc = 0; cc < 2; cc++) {
            uint32_t dst = base + P6_B + cc*PTILE;
            #pragma unroll
            for (int rep = 0; rep < 8; rep++) {
                int it = tid + rep*256;
                int row = it >> 4, q = it & 15;
                CP_ASYNC16(dst + row*PROW + q*16,
                           (const char*)(srcs[cc] + row*128) + q*16);
            }
        }
    }
    CP_COMMIT();
    CP_WAIT0();
    __syncthreads();

    const int tl = tid >> 2, qq = tid & 3;    // LN: 4 threads per token

    for (int tile = bid; tile < NP6; tile += NSM) {
        const int t0 = tile * 64;

        // --- LN(x) direct from gmem -> fp16 A ---
        {
            const float* xrow = x + (size_t)(t0 + tl)*CCH + qq*32;
            float v[32];
            float s = 0.f;
            #pragma unroll
            for (int i = 0; i < 8; i++) {
                float4 f = __ldg((const float4*)(xrow + i*4));
                v[i*4]=f.x; v[i*4+1]=f.y; v[i*4+2]=f.z; v[i*4+3]=f.w;
                s += f.x + f.y + f.z + f.w;
            }
            s += __shfl_xor_sync(0xFFFFFFFFu, s, 1);
            s += __shfl_xor_sync(0xFFFFFFFFu, s, 2);
            float m = s * (1.f/128.f);
            float q2 = 0.f;
            #pragma unroll
            for (int i = 0; i < 32; i++) { float d = v[i]-m; q2 += d*d; }
            q2 += __shfl_xor_sync(0xFFFFFFFFu, q2, 1);
            q2 += __shfl_xor_sync(0xFFFFFFFFu, q2, 2);
            float rs = rsqrtf(q2 * (1.f/128.f) + 1e-5f);

            #pragma unroll
            for (int i = 0; i < 16; i++) {
                int k = qq*32 + i*2;
                float v0 = (v[i*2]   - m)*rs*__ldg(&nw[k])   + __ldg(&nb[k]);
                float v1 = (v[i*2+1] - m)*rs*__ldg(&nw[k+1]) + __ldg(&nb[k+1]);
                __half2 hh;
                hh.x = __float2half_rn(v0);
                hh.y = __float2half_rn(v1);
                *(__half2*)(sm + P6_A + tl*PROW + k*2) = hh;
            }
        }
        __syncthreads();

        // --- 2 chunks, B resident ---
        #pragma unroll
        for (int c = 0; c < 2; c++) {
            const uint32_t sb = base + P6_B + c*PTILE;
            float acc[2][4][4];
            #pragma unroll
            for (int mt = 0; mt < 2; mt++)
                #pragma unroll
                for (int nt = 0; nt < 4; nt++)
                    #pragma unroll
                    for (int r = 0; r < 4; r++) acc[mt][nt][r] = 0.f;

            #pragma unroll
            for (int ks = 0; ks < 8; ks++) {
                const uint32_t koff = ks*32;
                uint32_t Ah[2][4];
                #pragma unroll
                for (int mt = 0; mt < 2; mt++) {
                    uint32_t r = (m_base + mt*16 + a_row)*PROW + koff + a_half*16;
                    ldsm4(Ah[mt], base + P6_A + r);
                }
                uint32_t Bf[4][2];
                #pragma unroll
                for (int p = 0; p < 2; p++) {
                    uint32_t r = (n_base + p*16 + b_row)*PROW + koff + b_half*16;
                    uint32_t th[4];
                    ldsm4(th, sb + r);
                    Bf[2*p][0]   = th[0]; Bf[2*p][1]   = th[1];
                    Bf[2*p+1][0] = th[2]; Bf[2*p+1][1] = th[3];
                }
                #pragma unroll
                for (int mt = 0; mt < 2; mt++)
                    #pragma unroll
                    for (int nt = 0; nt < 4; nt++) mma16816h(acc[mt][nt], Ah[mt], Bf[nt]);
            }

            // epilogue: transpose buffer, hi-only fp16
            uint32_t* tp = (uint32_t*)(sm + P6_TP);
            const int cgl = c * 64;
            #pragma unroll
            for (int mt = 0; mt < 2; mt++) {
                #pragma unroll
                for (int rp = 0; rp < 2; rp++) {
                    int t_loc = m_base + mt*16 + rp*8 + (lane >> 2);
                    float mk = (job == 0) ? __ldg(&mask[t0 + t_loc]) : 1.f;
                    #pragma unroll
                    for (int nt = 0; nt < 4; nt++) {
                        int c_loc = (n_base >> 1) + nt*4 + (lane & 3);
                        float val = sigmoidf_(acc[mt][nt][rp*2]) * acc[mt][nt][rp*2+1] * mk;
                        tp[c_loc*68 + t_loc] =
                            (uint32_t)__half_as_ushort(__float2half_rn(val));
                    }
                }
            }
            __syncthreads();

            uint32_t* dst = (uint32_t*)((job == 0) ? g_ahi : g_bhi);
            #pragma unroll
            for (int rep = 0; rep < 8; rep++) {
                int idx = tid + rep*256;        // 0..2047
                int cl = idx >> 5, t2 = idx & 31;
                uint32_t u0 = tp[cl*68 + t2*2];
                uint32_t u1 = tp[cl*68 + t2*2 + 1];
                uint32_t hi2 = (u0 & 0xFFFFu) | (u1 << 16);
                size_t o = ((size_t)(cgl + cl)*NTOK + t0) >> 1;
                dst[o + t2] = hi2;
            }
            __syncthreads();
        }
    }
}

// ---------------------------------------------------------------------------
// Kernel 2: tri einsum, single-pass fp16, K-chunk=128, triple buf, fp16 out.
// ---------------------------------------------------------------------------
#define TILE2   (128*PROW)          // 34816
#define CHUNKT  (2*TILE2)           // 69632
#define TRI_SMEM (3*CHUNKT)         // 208896

__device__ __forceinline__ void tri_load_chunk(
    uint32_t sbuf, const __half* sA, const __half* sB, int kk, int tid)
{
    const __half* srcs[2] = {sA, sB};
    #pragma unroll
    for (int rep = 0; rep < 16; rep++) {
        int it   = tid + rep*256;             // 0..4095
        int tile = it >> 11;
        int row  = (it >> 4) & 127;
        int q    = it & 15;
        const __half* gp = srcs[tile] + (size_t)row*SDIM + kk + q*8;
        CP_ASYNC16(sbuf + tile*TILE2 + row*PROW + q*16, gp);
    }
}

__global__ void __launch_bounds__(256) tri_mma_kernel()
{
    extern __shared__ char dynsm[];
    const uint32_t base = smem_u32(dynsm);

    const int tid  = threadIdx.x;
    const int wid  = tid >> 5;
    const int lane = tid & 31;
    const int m_base = (wid >> 2) * 64;
    const int n_base = (wid & 3) * 32;

    const int c  = blockIdx.y;
    const int i0 = (blockIdx.x / 6) * 128;
    const int j0 = (blockIdx.x % 6) * 128;

    const __half* sAh = g_ahi + (size_t)c*NTOK + (size_t)i0*SDIM;
    const __half* sBh = g_bhi + (size_t)c*NTOK + (size_t)j0*SDIM;

    float acc[4][4][4];
    #pragma unroll
    for (int mt = 0; mt < 4; mt++)
        #pragma unroll
        for (int nt = 0; nt < 4; nt++)
            #pragma unroll
            for (int r = 0; r < 4; r++) acc[mt][nt][r] = 0.f;

    const int a_row  = lane & 15;
    const int a_half = lane >> 4;
    const int b_quad = lane >> 3;
    const int b_row  = (b_quad >> 1) * 8 + (lane & 7);
    const int b_half = b_quad & 1;

    tri_load_chunk(base + 0*CHUNKT, sAh, sBh, 0,   tid); CP_COMMIT();
    tri_load_chunk(base + 1*CHUNKT, sAh, sBh, 128, tid); CP_COMMIT();

    for (int n = 0; n < 6; n++) {
        if (n + 2 < 6)
            tri_load_chunk(base + ((n+2)%3)*CHUNKT, sAh, sBh, (n+2)*128, tid);
        CP_COMMIT();
        CP_WAIT2();
        __syncthreads();

        const uint32_t sb = base + (n%3)*CHUNKT;
        #pragma unroll
        for (int ks = 0; ks < 8; ks++) {
            uint32_t Ah[4][4], Bh[4][2];
            const uint32_t koff = ks*32;
            #pragma unroll
            for (int mt = 0; mt < 4; mt++) {
                uint32_t r = (m_base + mt*16 + a_row)*PROW + koff + a_half*16;
                ldsm4(Ah[mt], sb + r);
            }
            #pragma unroll
            for (int p = 0; p < 2; p++) {
                uint32_t r = (n_base + p*16 + b_row)*PROW + koff + b_half*16;
                uint32_t th[4];
                ldsm4(th, sb + TILE2 + r);
                Bh[2*p][0]   = th[0]; Bh[2*p][1]   = th[1];
                Bh[2*p+1][0] = th[2]; Bh[2*p+1][1] = th[3];
            }
            #pragma unroll
            for (int mt = 0; mt < 4; mt++)
                #pragma unroll
                for (int nt = 0; nt < 4; nt++)
                    mma16816h(acc[mt][nt], Ah[mt], Bh[nt]);
        }
        __syncthreads();
    }

    __half* T = g_tri16 + (size_t)c*NTOK;
    const int er = i0 + m_base + (lane >> 2);
    const int ec2 = j0 + n_base + (lane & 3)*2;
    #pragma unroll
    for (int mt = 0; mt < 4; mt++) {
        #pragma unroll
        for (int nt = 0; nt < 4; nt++) {
            int rr = er + mt*16;
            int cc = ec2 + nt*8;
            __half2 v0; v0.x = __float2half_rn(acc[mt][nt][0]);
                        v0.y = __float2half_rn(acc[mt][nt][1]);
            __half2 v1; v1.x = __float2half_rn(acc[mt][nt][2]);
                        v1.y = __float2half_rn(acc[mt][nt][3]);
            *(__half2*)&T[(size_t)rr*SDIM + cc]     = v0;
            *(__half2*)&T[(size_t)(rr+8)*SDIM + cc] = v1;
        }
    }
}

// ---------------------------------------------------------------------------
// Kernel 3: out3 — persistent, 256 thr, 64-token tiles, 2 CTAs/SM.
// Computes gate = sigmoid(LN(x) @ wgo) AND out = (LN(tri) @ wpo) * gate.
// Gate MMA runs before the tri-staging wait (hides tri load latency).
// ---------------------------------------------------------------------------
#define TROW     144                    // 64 tok * 2B + 16 pad
#define O3_TRI   0                      // 128 ch x 144B = 18432
#define O3_A     18432                  // 64 x 272 = 17408
#define O3_BGO   (O3_A + ATILE)         // 35840
#define O3_BPO   (O3_BGO + PTILE)       // 70656
#define O3_SMEM  (O3_BPO + PTILE)       // 105472
#define NOT64    (NTOK/64)              // 9216
#define OGRID    (2*NSM)                // 296

__global__ void __launch_bounds__(256, 2) out3_kernel(
    const float* __restrict__ x,
    const float* __restrict__ niw, const float* __restrict__ nib,
    const float* __restrict__ now, const float* __restrict__ nob,
    float* __restrict__ out)
{
    extern __shared__ char sm[];
    const uint32_t base = smem_u32(sm);
    const int tid = threadIdx.x;
    const int bid = blockIdx.x;

    // one-time B tiles (wgo^T, wpo^T fp16)
    #pragma unroll
    for (int rep = 0; rep < 8; rep++) {
        int it = tid + rep*256;
        int row = it >> 4, q = it & 15;
        CP_ASYNC16(base + O3_BGO + row*PROW + q*16,
                   (const char*)(g_wgo16 + row*128) + q*16);
        CP_ASYNC16(base + O3_BPO + row*PROW + q*16,
                   (const char*)(g_wpo16 + row*128) + q*16);
    }
    // first tri tile (fp16, 64 tokens)
    {
        int t0 = bid * 64;
        #pragma unroll
        for (int rep = 0; rep < 4; rep++) {
            int it = tid + rep*256;           // 0..1023
            int ch = it >> 3, q = it & 7;
            CP_ASYNC16(base + O3_TRI + ch*TROW + q*16,
                       g_tri16 + (size_t)ch*NTOK + t0 + q*8);
        }
    }
    CP_COMMIT();

    const int wid  = tid >> 5;
    const int lane = tid & 31;
    const int m_base = (wid >> 2) * 32;
    const int n_base = (wid & 3) * 32;
    const int a_row  = lane & 15;
    const int a_half = lane >> 4;
    const int b_quad = lane >> 3;
    const int b_row  = (b_quad >> 1)*8 + (lane & 7);
    const int b_half = b_quad & 1;
    const int er = m_base + (lane >> 2);
    const int ec = n_base + (lane & 3)*2;

    const __half* trs = (const __half*)(sm + O3_TRI);
    const int tl = tid >> 2, qq = tid & 3;

    bool first = true;
    for (int tile = bid; tile < NOT64; tile += OGRID) {
        const int t0 = tile * 64;

        // --- LN(x) -> A (doesn't need tri staging) ---
        if (first) { CP_WAIT0(); first = false; }  // ensure B tiles present
        __syncthreads();   // A free from previous iteration
        {
            const float* xrow = x + (size_t)(t0 + tl)*CCH + qq*32;
            float v[32];
            float s = 0.f;
            #pragma unroll
            for (int i = 0; i < 8; i++) {
                float4 f = __ldg((const float4*)(xrow + i*4));
                v[i*4]=f.x; v[i*4+1]=f.y; v[i*4+2]=f.z; v[i*4+3]=f.w;
                s += f.x + f.y + f.z + f.w;
            }
            s += __shfl_xor_sync(0xFFFFFFFFu, s, 1);
            s += __shfl_xor_sync(0xFFFFFFFFu, s, 2);
            float m = s * (1.f/128.f);
            float q2 = 0.f;
            #pragma unroll
            for (int i = 0; i < 32; i++) { float d = v[i]-m; q2 += d*d; }
            q2 += __shfl_xor_sync(0xFFFFFFFFu, q2, 1);
            q2 += __shfl_xor_sync(0xFFFFFFFFu, q2, 2);
            float rs = rsqrtf(q2 * (1.f/128.f) + 1e-5f);

            #pragma unroll
            for (int i = 0; i < 16; i++) {
                int k = qq*32 + i*2;
                float v0 = (v[i*2]   - m)*rs*__ldg(&niw[k])   + __ldg(&nib[k]);
                float v1 = (v[i*2+1] - m)*rs*__ldg(&niw[k+1]) + __ldg(&nib[k+1]);
                __half2 hh;
                hh.x = __float2half_rn(v0);
                hh.y = __float2half_rn(v1);
                *(__half2*)(sm + O3_A + tl*PROW + k*2) = hh;
            }
        }
        __syncthreads();

        // --- gate MMA: A x wgo ---
        float accg[2][4][4];
        #pragma unroll
        for (int mt = 0; mt < 2; mt++)
            #pragma unroll
            for (int nt = 0; nt < 4; nt++)
                #pragma unroll
                for (int r = 0; r < 4; r++) accg[mt][nt][r] = 0.f;
        #pragma unroll
        for (int ks = 0; ks < 8; ks++) {
            const uint32_t koff = ks*32;
            uint32_t Ah[2][4];
            #pragma unroll
            for (int mt = 0; mt < 2; mt++) {
                uint32_t r = (m_base + mt*16 + a_row)*PROW + koff + a_half*16;
                ldsm4(Ah[mt], base + O3_A + r);
            }
            uint32_t Bf[4][2];
            #pragma unroll
            for (int p = 0; p < 2; p++) {
                uint32_t r = (n_base + p*16 + b_row)*PROW + koff + b_half*16;
                uint32_t th[4];
                ldsm4(th, base + O3_BGO + r);
                Bf[2*p][0]   = th[0]; Bf[2*p][1]   = th[1];
                Bf[2*p+1][0] = th[2]; Bf[2*p+1][1] = th[3];
            }
            #pragma unroll
            for (int mt = 0; mt < 2; mt++)
                #pragma unroll
                for (int nt = 0; nt < 4; nt++) mma16816h(accg[mt][nt], Ah[mt], Bf[nt]);
        }
        __syncthreads();   // done reading A

        // --- tri ready? LN(tri) -> A ---
        CP_WAIT0();
        __syncthreads();
        {
            float s = 0.f;
            float vch[32];
            #pragma unroll
            for (int j = 0; j < 32; j++) {
                vch[j] = __half2float(trs[(qq*32 + j)*72 + tl]);
                s += vch[j];
            }
            s += __shfl_xor_sync(0xFFFFFFFFu, s, 1);
            s += __shfl_xor_sync(0xFFFFFFFFu, s, 2);
            float m = s * (1.f/128.f);
            float q2 = 0.f;
            #pragma unroll
            for (int j = 0; j < 32; j++) {
                float d = vch[j] - m;
                q2 += d*d;
            }
            q2 += __shfl_xor_sync(0xFFFFFFFFu, q2, 1);
            q2 += __shfl_xor_sync(0xFFFFFFFFu, q2, 2);
            float rs = rsqrtf(q2 * (1.f/128.f) + 1e-5f);

            #pragma unroll
            for (int j = 0; j < 16; j++) {
                int ch = qq*32 + j*2;
                float v0 = (vch[j*2]   - m)*rs*__ldg(&now[ch])   + __ldg(&nob[ch]);
                float v1 = (vch[j*2+1] - m)*rs*__ldg(&now[ch+1]) + __ldg(&nob[ch+1]);
                __half2 hh;
                hh.x = __float2half_rn(v0);
                hh.y = __float2half_rn(v1);
                *(__half2*)(sm + O3_A + tl*PROW + ch*2) = hh;
            }
        }
        __syncthreads();

        // prefetch next tri tile into staging (LN consumed it)
        if (tile + OGRID < NOT64) {
            int nt0 = (tile + OGRID) * 64;
            #pragma unroll
            for (int rep = 0; rep < 4; rep++) {
                int it = tid + rep*256;
                int ch = it >> 3, q = it & 7;
                CP_ASYNC16(base + O3_TRI + ch*TROW + q*16,
                           g_tri16 + (size_t)ch*NTOK + nt0 + q*8);
            }
        }
        CP_COMMIT();

        // --- out MMA: A x wpo ---
        float acc[2][4][4];
        #pragma unroll
        for (int mt = 0; mt < 2; mt++)
            #pragma unroll
            for (int nt = 0; nt < 4; nt++)
                #pragma unroll
                for (int r = 0; r < 4; r++) acc[mt][nt][r] = 0.f;
        #pragma unroll
        for (int ks = 0; ks < 8; ks++) {
            const uint32_t koff = ks*32;
            uint32_t Ah[2][4];
            #pragma unroll
            for (int mt = 0; mt < 2; mt++) {
                uint32_t r = (m_base + mt*16 + a_row)*PROW + koff + a_half*16;
                ldsm4(Ah[mt], base + O3_A + r);
            }
            uint32_t Bf[4][2];
            #pragma unroll
            for (int p = 0; p < 2; p++) {
                uint32_t r = (n_base + p*16 + b_row)*PROW + koff + b_half*16;
                uint32_t th[4];
                ldsm4(th, base + O3_BPO + r);
                Bf[2*p][0]   = th[0]; Bf[2*p][1]   = th[1];
                Bf[2*p+1][0] = th[2]; Bf[2*p+1][1] = th[3];
            }
            #pragma unroll
            for (int mt = 0; mt < 2; mt++)
                #pragma unroll
                for (int nt = 0; nt < 4; nt++) mma16816h(acc[mt][nt], Ah[mt], Bf[nt]);
        }

        // --- epilogue: out = acc * sigmoid(accg), fragment-aligned ---
        #pragma unroll
        for (int mt = 0; mt < 2; mt++) {
            #pragma unroll
            for (int rp = 0; rp < 2; rp++) {
                int t = t0 + er + mt*16 + rp*8;
                #pragma unroll
                for (int nt = 0; nt < 4; nt++) {
                    int cc = ec + nt*8;
                    float2 o = make_float2(
                        acc[mt][nt][rp*2]   * sigmoidf_(accg[mt][nt][rp*2]),
                        acc[mt][nt][rp*2+1] * sigmoidf_(accg[mt][nt][rp*2+1]));
                    *(float2*)&out[(size_t)t*CCH + cc] = o;
                }
            }
        }
    }
}

// ---------------------------------------------------------------------------
extern "C" void kernel_launch(void* const* d_in, const int* in_sizes, int n_in,
                              void* d_out, int out_size)
{
    const float* x    = (const float*)d_in[0];
    const float* mask = (const float*)d_in[1];
    const float* niw  = (const float*)d_in[2];
    const float* nib  = (const float*)d_in[3];
    const float* wgi  = (const float*)d_in[4];
    const float* wpi  = (const float*)d_in[5];
    const float* now  = (const float*)d_in[6];
    const float* nob  = (const float*)d_in[7];
    const float* wgo  = (const float*)d_in[8];
    const float* wpo  = (const float*)d_in[9];
    float* out = (float*)d_out;

    cudaFuncSetAttribute(proj6_kernel,
        cudaFuncAttributeMaxDynamicSharedMemorySize, P6_SMEM);
    cudaFuncSetAttribute(tri_mma_kernel,
        cudaFuncAttributeMaxDynamicSharedMemorySize, TRI_SMEM);
    cudaFuncSetAttribute(out3_kernel,
        cudaFuncAttributeMaxDynamicSharedMemorySize, O3_SMEM);

    prep_w_kernel<<<256, 256>>>(wgi, wpi, wgo, wpo);
    proj6_kernel<<<dim3(NSM, 2), 256, P6_SMEM>>>(x, mask, niw, nib);
    tri_mma_kernel<<<dim3(36, 128), 256, TRI_SMEM>>>();
    out3_kernel<<<OGRID, 256, O3_SMEM>>>(x, niw, nib, now, nob, out);
}

// round 13
// speedup vs baseline: 1.5946x; 1.5946x over previous
#include <cuda_runtime.h>
#include <cuda_bf16.h>
#include <cuda_fp16.h>
#include <math.h>
#include <stdint.h>

#define SDIM 768
#define CCH  128
#define NTOK (SDIM*SDIM)        // 589824 tokens
#define SELEM 75497472          // 128 * 589824
#define NSM   148

// Scratch: a, b, tri, gate all fp16
__device__ __half g_ahi[SELEM];
__device__ __half g_bhi[SELEM];
__device__ __half g_tri16[SELEM];
__device__ __half g_gate16[SELEM];

// Prepped fp16 weights:
// g_wcI: 4 groups x 128 rows x 128 k; group g row 2r = wgi col(64g+r), row 2r+1 = wpi col(64g+r)
__device__ __half g_wcI[4*128*128];
__device__ __half g_wgo16[128*128];   // wgo^T [n][k]
__device__ __half g_wpo16[128*128];   // wpo^T [co][h]

__device__ __forceinline__ float sigmoidf_(float v) {
    return 1.f / (1.f + __expf(-v));
}
__device__ __forceinline__ uint32_t smem_u32(const void* p) {
    uint32_t a;
    asm("{ .reg .u64 t; cvta.to.shared.u64 t, %1; cvt.u32.u64 %0, t; }"
        : "=r"(a) : "l"(p));
    return a;
}
#define CP_ASYNC16(d, s)  asm volatile("cp.async.cg.shared.global [%0], [%1], 16;" :: "r"(d), "l"(s))
#define CP_COMMIT()       asm volatile("cp.async.commit_group;" ::: "memory")
#define CP_WAIT0()        asm volatile("cp.async.wait_group 0;" ::: "memory")
#define CP_WAIT2()        asm volatile("cp.async.wait_group 2;" ::: "memory")

__device__ __forceinline__ void ldsm4(uint32_t* r, uint32_t addr) {
    asm volatile("ldmatrix.sync.aligned.m8n8.x4.shared.b16 {%0,%1,%2,%3}, [%4];"
        : "=r"(r[0]), "=r"(r[1]), "=r"(r[2]), "=r"(r[3]) : "r"(addr));
}
__device__ __forceinline__ void mma16816h(float* d, const uint32_t* a, const uint32_t* b) {
    asm volatile("mma.sync.aligned.m16n8k16.row.col.f32.f16.f16.f32 "
        "{%0,%1,%2,%3}, {%4,%5,%6,%7}, {%8,%9}, {%0,%1,%2,%3};"
        : "+f"(d[0]), "+f"(d[1]), "+f"(d[2]), "+f"(d[3])
        : "r"(a[0]), "r"(a[1]), "r"(a[2]), "r"(a[3]), "r"(b[0]), "r"(b[1]));
}

// ---------------------------------------------------------------------------
// Kernel 0: weight prep.
// ---------------------------------------------------------------------------
__global__ void __launch_bounds__(256) prep_w_kernel(
    const float* __restrict__ wgi, const float* __restrict__ wpi,
    const float* __restrict__ wgo, const float* __restrict__ wpo)
{
    int idx = blockIdx.x*256 + threadIdx.x;   // 0..65535
    {
        int g = idx >> 14, rem = idx & 16383;
        int row = rem >> 7, k = rem & 127;
        int col = g*64 + (row >> 1);
        float v = (row & 1) ? wpi[k*256 + col] : wgi[k*256 + col];
        g_wcI[idx] = __float2half_rn(v);
    }
    if (idx < 16384) {
        int n = idx >> 7, k = idx & 127;
        g_wgo16[idx] = __float2half_rn(wgo[k*128 + n]);
        g_wpo16[idx] = __float2half_rn(wpo[k*128 + n]);
    }
}

// ---------------------------------------------------------------------------
// Kernel 1: proj5r — persistent; 64-token tiles; 5 weight chunks smem-resident;
// single-pass fp16; A fragments HOISTED to registers (loaded once per tile).
// ---------------------------------------------------------------------------
#define PROW   272
#define PTILE  (128*PROW)         // 34816
#define ATILE  (64*PROW)          // 17408
#define P5_A    0
#define P5_B    ATILE                      // 17408
#define P5_TP   (P5_B + 5*PTILE)           // 191488
#define P5_SMEM (P5_TP + 64*68*4)          // 208896
#define NP5     (NTOK/64)                  // 9216

__global__ void __launch_bounds__(256) proj5r_kernel(
    const float* __restrict__ x, const float* __restrict__ mask,
    const float* __restrict__ nw, const float* __restrict__ nb)
{
    extern __shared__ char sm[];
    const uint32_t base = smem_u32(sm);
    const int tid = threadIdx.x;
    const int bid = blockIdx.x;

    const int wid  = tid >> 5;
    const int lane = tid & 31;
    const int m_base = (wid >> 2) * 32;
    const int n_base = (wid & 3) * 32;
    const int a_row  = lane & 15;
    const int a_half = lane >> 4;
    const int b_quad = lane >> 3;
    const int b_row  = (b_quad >> 1)*8 + (lane & 7);
    const int b_half = b_quad & 1;

    // --- load ALL 5 B chunks once ---
    const __half* csrc[5] = { g_wcI, g_wcI + 16384, g_wcI + 32768,
                              g_wcI + 49152, g_wgo16 };
    for (int cc = 0; cc < 5; cc++) {
        const __half* s = csrc[cc];
        uint32_t dst = base + P5_B + cc*PTILE;
        #pragma unroll
        for (int rep = 0; rep < 8; rep++) {
            int it = tid + rep*256;
            int row = it >> 4, q = it & 15;
            CP_ASYNC16(dst + row*PROW + q*16, (const char*)(s + row*128) + q*16);
        }
    }
    CP_COMMIT();
    CP_WAIT0();
    __syncthreads();

    const int tl = tid >> 2, qq = tid & 3;    // LN: 4 threads per token

    for (int tile = bid; tile < NP5; tile += NSM) {
        const int t0 = tile * 64;

        // --- LN(x) direct from gmem -> fp16 A (hi only) ---
        {
            const float* xrow = x + (size_t)(t0 + tl)*CCH + qq*32;
            float v[32];
            float s = 0.f;
            #pragma unroll
            for (int i = 0; i < 8; i++) {
                float4 f = __ldg((const float4*)(xrow + i*4));
                v[i*4]=f.x; v[i*4+1]=f.y; v[i*4+2]=f.z; v[i*4+3]=f.w;
                s += f.x + f.y + f.z + f.w;
            }
            s += __shfl_xor_sync(0xFFFFFFFFu, s, 1);
            s += __shfl_xor_sync(0xFFFFFFFFu, s, 2);
            float m = s * (1.f/128.f);
            float q2 = 0.f;
            #pragma unroll
            for (int i = 0; i < 32; i++) { float d = v[i]-m; q2 += d*d; }
            q2 += __shfl_xor_sync(0xFFFFFFFFu, q2, 1);
            q2 += __shfl_xor_sync(0xFFFFFFFFu, q2, 2);
            float rs = rsqrtf(q2 * (1.f/128.f) + 1e-5f);

            #pragma unroll
            for (int i = 0; i < 16; i++) {
                int k = qq*32 + i*2;
                float v0 = (v[i*2]   - m)*rs*__ldg(&nw[k])   + __ldg(&nb[k]);
                float v1 = (v[i*2+1] - m)*rs*__ldg(&nw[k+1]) + __ldg(&nb[k+1]);
                __half2 hh;
                hh.x = __float2half_rn(v0);
                hh.y = __float2half_rn(v1);
                *(__half2*)(sm + P5_A + tl*PROW + k*2) = hh;
            }
        }
        __syncthreads();

        // --- hoist A fragments to registers (once per tile) ---
        uint32_t Af[8][2][4];
        #pragma unroll
        for (int ks = 0; ks < 8; ks++) {
            const uint32_t koff = ks*32;
            #pragma unroll
            for (int mt = 0; mt < 2; mt++) {
                uint32_t r = (m_base + mt*16 + a_row)*PROW + koff + a_half*16;
                ldsm4(Af[ks][mt], base + P5_A + r);
            }
        }

        // --- 5 chunks, B resident, A in registers ---
        #pragma unroll
        for (int c = 0; c < 5; c++) {
            const uint32_t sb = base + P5_B + c*PTILE;
            float acc[2][4][4];
            #pragma unroll
            for (int mt = 0; mt < 2; mt++)
                #pragma unroll
                for (int nt = 0; nt < 4; nt++)
                    #pragma unroll
                    for (int r = 0; r < 4; r++) acc[mt][nt][r] = 0.f;

            #pragma unroll
            for (int ks = 0; ks < 8; ks++) {
                const uint32_t koff = ks*32;
                uint32_t Bf[4][2];
                #pragma unroll
                for (int p = 0; p < 2; p++) {
                    uint32_t r = (n_base + p*16 + b_row)*PROW + koff + b_half*16;
                    uint32_t th[4];
                    ldsm4(th, sb + r);
                    Bf[2*p][0]   = th[0]; Bf[2*p][1]   = th[1];
                    Bf[2*p+1][0] = th[2]; Bf[2*p+1][1] = th[3];
                }
                #pragma unroll
                for (int mt = 0; mt < 2; mt++)
                    #pragma unroll
                    for (int nt = 0; nt < 4; nt++)
                        mma16816h(acc[mt][nt], Af[ks][mt], Bf[nt]);
            }

            if (c < 4) {
                // a/b epilogue: hi-only via transpose buffer
                uint32_t* tp = (uint32_t*)(sm + P5_TP);
                const bool isA = (c < 2);
                const int cgl = (c & 1) * 64;
                #pragma unroll
                for (int mt = 0; mt < 2; mt++) {
                    #pragma unroll
                    for (int rp = 0; rp < 2; rp++) {
                        int t_loc = m_base + mt*16 + rp*8 + (lane >> 2);
                        float mk = isA ? __ldg(&mask[t0 + t_loc]) : 1.f;
                        #pragma unroll
                        for (int nt = 0; nt < 4; nt++) {
                            int c_loc = (n_base >> 1) + nt*4 + (lane & 3);
                            float val = sigmoidf_(acc[mt][nt][rp*2]) * acc[mt][nt][rp*2+1] * mk;
                            tp[c_loc*68 + t_loc] =
                                (uint32_t)__half_as_ushort(__float2half_rn(val));
                        }
                    }
                }
                __syncthreads();

                #pragma unroll
                for (int rep = 0; rep < 8; rep++) {
                    int idx = tid + rep*256;        // 0..2047
                    int cl = idx >> 5, t2 = idx & 31;
                    uint32_t u0 = tp[cl*68 + t2*2];
                    uint32_t u1 = tp[cl*68 + t2*2 + 1];
                    uint32_t hi2 = (u0 & 0xFFFFu) | (u1 << 16);
                    size_t o = ((size_t)(cgl + cl)*NTOK + t0) >> 1;
                    if (isA) ((uint32_t*)g_ahi)[o + t2] = hi2;
                    else     ((uint32_t*)g_bhi)[o + t2] = hi2;
                }
                __syncthreads();
            } else {
                // out-gate epilogue: token-major sigmoid -> fp16
                #pragma unroll
                for (int mt = 0; mt < 2; mt++) {
                    #pragma unroll
                    for (int rp = 0; rp < 2; rp++) {
                        int t = t0 + m_base + mt*16 + rp*8 + (lane >> 2);
                        #pragma unroll
                        for (int nt = 0; nt < 4; nt++) {
                            int ch = n_base + nt*8 + (lane & 3)*2;
                            __half2 f;
                            f.x = __float2half_rn(sigmoidf_(acc[mt][nt][rp*2]));
                            f.y = __float2half_rn(sigmoidf_(acc[mt][nt][rp*2+1]));
                            *(__half2*)&g_gate16[(size_t)t*CCH + ch] = f;
                        }
                    }
                }
            }
        }
        __syncthreads();
    }
}

// ---------------------------------------------------------------------------
// Kernel 2: tri einsum, single-pass fp16, K-chunk=128, triple buf, fp16 out.
// ---------------------------------------------------------------------------
#define TILE2   (128*PROW)          // 34816
#define CHUNKT  (2*TILE2)           // 69632
#define TRI_SMEM (3*CHUNKT)         // 208896

__device__ __forceinline__ void tri_load_chunk(
    uint32_t sbuf, const __half* sA, const __half* sB, int kk, int tid)
{
    const __half* srcs[2] = {sA, sB};
    #pragma unroll
    for (int rep = 0; rep < 16; rep++) {
        int it   = tid + rep*256;             // 0..4095
        int tile = it >> 11;
        int row  = (it >> 4) & 127;
        int q    = it & 15;
        const __half* gp = srcs[tile] + (size_t)row*SDIM + kk + q*8;
        CP_ASYNC16(sbuf + tile*TILE2 + row*PROW + q*16, gp);
    }
}

__global__ void __launch_bounds__(256) tri_mma_kernel()
{
    extern __shared__ char dynsm[];
    const uint32_t base = smem_u32(dynsm);

    const int tid  = threadIdx.x;
    const int wid  = tid >> 5;
    const int lane = tid & 31;
    const int m_base = (wid >> 2) * 64;
    const int n_base = (wid & 3) * 32;

    const int c  = blockIdx.y;
    const int i0 = (blockIdx.x / 6) * 128;
    const int j0 = (blockIdx.x % 6) * 128;

    const __half* sAh = g_ahi + (size_t)c*NTOK + (size_t)i0*SDIM;
    const __half* sBh = g_bhi + (size_t)c*NTOK + (size_t)j0*SDIM;

    float acc[4][4][4];
    #pragma unroll
    for (int mt = 0; mt < 4; mt++)
        #pragma unroll
        for (int nt = 0; nt < 4; nt++)
            #pragma unroll
            for (int r = 0; r < 4; r++) acc[mt][nt][r] = 0.f;

    const int a_row  = lane & 15;
    const int a_half = lane >> 4;
    const int b_quad = lane >> 3;
    const int b_row  = (b_quad >> 1) * 8 + (lane & 7);
    const int b_half = b_quad & 1;

    tri_load_chunk(base + 0*CHUNKT, sAh, sBh, 0,   tid); CP_COMMIT();
    tri_load_chunk(base + 1*CHUNKT, sAh, sBh, 128, tid); CP_COMMIT();

    for (int n = 0; n < 6; n++) {
        if (n + 2 < 6)
            tri_load_chunk(base + ((n+2)%3)*CHUNKT, sAh, sBh, (n+2)*128, tid);
        CP_COMMIT();
        CP_WAIT2();
        __syncthreads();

        const uint32_t sb = base + (n%3)*CHUNKT;
        #pragma unroll
        for (int ks = 0; ks < 8; ks++) {
            uint32_t Ah[4][4], Bh[4][2];
            const uint32_t koff = ks*32;
            #pragma unroll
            for (int mt = 0; mt < 4; mt++) {
                uint32_t r = (m_base + mt*16 + a_row)*PROW + koff + a_half*16;
                ldsm4(Ah[mt], sb + r);
            }
            #pragma unroll
            for (int p = 0; p < 2; p++) {
                uint32_t r = (n_base + p*16 + b_row)*PROW + koff + b_half*16;
                uint32_t th[4];
                ldsm4(th, sb + TILE2 + r);
                Bh[2*p][0]   = th[0]; Bh[2*p][1]   = th[1];
                Bh[2*p+1][0] = th[2]; Bh[2*p+1][1] = th[3];
            }
            #pragma unroll
            for (int mt = 0; mt < 4; mt++)
                #pragma unroll
                for (int nt = 0; nt < 4; nt++)
                    mma16816h(acc[mt][nt], Ah[mt], Bh[nt]);
        }
        __syncthreads();
    }

    __half* T = g_tri16 + (size_t)c*NTOK;
    const int er = i0 + m_base + (lane >> 2);
    const int ec2 = j0 + n_base + (lane & 3)*2;
    #pragma unroll
    for (int mt = 0; mt < 4; mt++) {
        #pragma unroll
        for (int nt = 0; nt < 4; nt++) {
            int rr = er + mt*16;
            int cc = ec2 + nt*8;
            __half2 v0; v0.x = __float2half_rn(acc[mt][nt][0]);
                        v0.y = __float2half_rn(acc[mt][nt][1]);
            __half2 v1; v1.x = __float2half_rn(acc[mt][nt][2]);
                        v1.y = __float2half_rn(acc[mt][nt][3]);
            *(__half2*)&T[(size_t)rr*SDIM + cc]     = v0;
            *(__half2*)&T[(size_t)(rr+8)*SDIM + cc] = v1;
        }
    }
}

// ---------------------------------------------------------------------------
// Kernel 3: out2 — persistent, 256 thr, 64-token tiles, 2 CTAs/SM.
// tri fp16 staging, single-pass fp16 MMA, gate fp16 LDG. (R11 exact)
// ---------------------------------------------------------------------------
#define TROW     144                    // 64 tok * 2B + 16 pad
#define O2_TRI   0                      // 128 ch x 144B = 18432
#define O2_A     18432                  // 64 x 272 = 17408
#define O2_B     (O2_A + ATILE)         // 35840
#define O2_SMEM  (O2_B + PTILE)         // 70656  (2 CTAs/SM)
#define NOT64    (NTOK/64)              // 9216
#define OGRID    (2*NSM)                // 296

__global__ void __launch_bounds__(256) out2_kernel(
    const float* __restrict__ now, const float* __restrict__ nob,
    float* __restrict__ out)
{
    extern __shared__ char sm[];
    const uint32_t base = smem_u32(sm);
    const int tid = threadIdx.x;
    const int bid = blockIdx.x;

    // one-time B (wpo^T fp16)
    #pragma unroll
    for (int rep = 0; rep < 8; rep++) {
        int it = tid + rep*256;
        int row = it >> 4, q = it & 15;
        CP_ASYNC16(base + O2_B + row*PROW + q*16,
                   (const char*)(g_wpo16 + row*128) + q*16);
    }
    // first tri tile (fp16, 64 tokens)
    {
        int t0 = bid * 64;
        #pragma unroll
        for (int rep = 0; rep < 4; rep++) {
            int it = tid + rep*256;           // 0..1023
            int ch = it >> 3, q = it & 7;
            CP_ASYNC16(base + O2_TRI + ch*TROW + q*16,
                       g_tri16 + (size_t)ch*NTOK + t0 + q*8);
        }
    }
    CP_COMMIT();

    const int wid  = tid >> 5;
    const int lane = tid & 31;
    const int m_base = (wid >> 2) * 32;
    const int n_base = (wid & 3) * 32;
    const int a_row  = lane & 15;
    const int a_half = lane >> 4;
    const int b_quad = lane >> 3;
    const int b_row  = (b_quad >> 1)*8 + (lane & 7);
    const int b_half = b_quad & 1;
    const int er = m_base + (lane >> 2);
    const int ec = n_base + (lane & 3)*2;

    const __half* trs = (const __half*)(sm + O2_TRI);
    const int tl = tid >> 2, qq = tid & 3;

    for (int tile = bid; tile < NOT64; tile += OGRID) {
        const int t0 = tile * 64;
        CP_WAIT0();
        __syncthreads();

        // LN over channels (fp16 staging) -> fp16 A [t][ch]
        {
            float s = 0.f;
            float vch[32];
            #pragma unroll
            for (int j = 0; j < 32; j++) {
                vch[j] = __half2float(trs[(qq*32 + j)*72 + tl]);
                s += vch[j];
            }
            s += __shfl_xor_sync(0xFFFFFFFFu, s, 1);
            s += __shfl_xor_sync(0xFFFFFFFFu, s, 2);
            float m = s * (1.f/128.f);
            float q2 = 0.f;
            #pragma unroll
            for (int j = 0; j < 32; j++) {
                float d = vch[j] - m;
                q2 += d*d;
            }
            q2 += __shfl_xor_sync(0xFFFFFFFFu, q2, 1);
            q2 += __shfl_xor_sync(0xFFFFFFFFu, q2, 2);
            float rs = rsqrtf(q2 * (1.f/128.f) + 1e-5f);

            #pragma unroll
            for (int j = 0; j < 16; j++) {
                int ch = qq*32 + j*2;
                float v0 = (vch[j*2]   - m)*rs*__ldg(&now[ch])   + __ldg(&nob[ch]);
                float v1 = (vch[j*2+1] - m)*rs*__ldg(&now[ch+1]) + __ldg(&nob[ch+1]);
                __half2 hh;
                hh.x = __float2half_rn(v0);
                hh.y = __float2half_rn(v1);
                *(__half2*)(sm + O2_A + tl*PROW + ch*2) = hh;
            }
        }
        __syncthreads();

        // prefetch next tri tile into staging
        if (tile + OGRID < NOT64) {
            int nt0 = (tile + OGRID) * 64;
            #pragma unroll
            for (int rep = 0; rep < 4; rep++) {
                int it = tid + rep*256;
                int ch = it >> 3, q = it & 7;
                CP_ASYNC16(base + O2_TRI + ch*TROW + q*16,
                           g_tri16 + (size_t)ch*NTOK + nt0 + q*8);
            }
        }
        CP_COMMIT();

        float acc[2][4][4];
        #pragma unroll
        for (int mt = 0; mt < 2; mt++)
            #pragma unroll
            for (int nt = 0; nt < 4; nt++)
                #pragma unroll
                for (int r = 0; r < 4; r++) acc[mt][nt][r] = 0.f;

        #pragma unroll
        for (int ks = 0; ks < 8; ks++) {
            const uint32_t koff = ks*32;
            uint32_t Ah[2][4];
            #pragma unroll
            for (int mt = 0; mt < 2; mt++) {
                uint32_t r = (m_base + mt*16 + a_row)*PROW + koff + a_half*16;
                ldsm4(Ah[mt], base + O2_A + r);
            }
            uint32_t Bf[4][2];
            #pragma unroll
            for (int p = 0; p < 2; p++) {
                uint32_t r = (n_base + p*16 + b_row)*PROW + koff + b_half*16;
                uint32_t th[4];
                ldsm4(th, base + O2_B + r);
                Bf[2*p][0]   = th[0]; Bf[2*p][1]   = th[1];
                Bf[2*p+1][0] = th[2]; Bf[2*p+1][1] = th[3];
            }
            #pragma unroll
            for (int mt = 0; mt < 2; mt++)
                #pragma unroll
                for (int nt = 0; nt < 4; nt++) mma16816h(acc[mt][nt], Ah[mt], Bf[nt]);
        }

        // epilogue: gate fp16 via direct LDG, out stores
        #pragma unroll
        for (int mt = 0; mt < 2; mt++) {
            #pragma unroll
            for (int rp = 0; rp < 2; rp++) {
                int t = t0 + er + mt*16 + rp*8;
                #pragma unroll
                for (int nt = 0; nt < 4; nt++) {
                    int cc = ec + nt*8;
                    __half2 gh = __ldg((const __half2*)&g_gate16[(size_t)t*CCH + cc]);
                    float2 o = make_float2(acc[mt][nt][rp*2]   * __half2float(gh.x),
                                           acc[mt][nt][rp*2+1] * __half2float(gh.y));
                    *(float2*)&out[(size_t)t*CCH + cc] = o;
                }
            }
        }
        __syncthreads();
    }
}

// ---------------------------------------------------------------------------
extern "C" void kernel_launch(void* const* d_in, const int* in_sizes, int n_in,
                              void* d_out, int out_size)
{
    const float* x    = (const float*)d_in[0];
    const float* mask = (const float*)d_in[1];
    const float* niw  = (const float*)d_in[2];
    const float* nib  = (const float*)d_in[3];
    const float* wgi  = (const float*)d_in[4];
    const float* wpi  = (const float*)d_in[5];
    const float* now  = (const float*)d_in[6];
    const float* nob  = (const float*)d_in[7];
    const float* wgo  = (const float*)d_in[8];
    const float* wpo  = (const float*)d_in[9];
    float* out = (float*)d_out;

    cudaFuncSetAttribute(proj5r_kernel,
        cudaFuncAttributeMaxDynamicSharedMemorySize, P5_SMEM);
    cudaFuncSetAttribute(tri_mma_kernel,
        cudaFuncAttributeMaxDynamicSharedMemorySize, TRI_SMEM);
    cudaFuncSetAttribute(out2_kernel,
        cudaFuncAttributeMaxDynamicSharedMemorySize, O2_SMEM);

    prep_w_kernel<<<256, 256>>>(wgi, wpi, wgo, wpo);
    proj5r_kernel<<<NSM, 256, P5_SMEM>>>(x, mask, niw, nib);
    tri_mma_kernel<<<dim3(36, 128), 256, TRI_SMEM>>>();
    out2_kernel<<<OGRID, 256, O2_SMEM>>>(now, nob, out);
}

// round 14
// speedup vs baseline: 1.7488x; 1.0967x over previous
#include <cuda_runtime.h>
#include <cuda_bf16.h>
#include <cuda_fp16.h>
#include <math.h>
#include <stdint.h>

#define SDIM 768
#define CCH  128
#define NTOK (SDIM*SDIM)        // 589824 tokens
#define SELEM 75497472          // 128 * 589824
#define NSM   148

// Scratch: a, b, tri, gate all fp16
__device__ __half g_ahi[SELEM];
__device__ __half g_bhi[SELEM];
__device__ __half g_tri16[SELEM];
__device__ __half g_gate16[SELEM];

// Prepped fp16 weights:
// g_wcI: 4 groups x 128 rows x 128 k; group g row 2r = wgi col(64g+r), row 2r+1 = wpi col(64g+r)
__device__ __half g_wcI[4*128*128];
__device__ __half g_wgo16[128*128];   // wgo^T [n][k]
__device__ __half g_wpo16[128*128];   // wpo^T [co][h]

__device__ __forceinline__ float sigmoidf_(float v) {
    return 1.f / (1.f + __expf(-v));
}
__device__ __forceinline__ uint32_t smem_u32(const void* p) {
    uint32_t a;
    asm("{ .reg .u64 t; cvta.to.shared.u64 t, %1; cvt.u32.u64 %0, t; }"
        : "=r"(a) : "l"(p));
    return a;
}
#define CP_ASYNC16(d, s)  asm volatile("cp.async.cg.shared.global [%0], [%1], 16;" :: "r"(d), "l"(s))
#define CP_COMMIT()       asm volatile("cp.async.commit_group;" ::: "memory")
#define CP_WAIT0()        asm volatile("cp.async.wait_group 0;" ::: "memory")
#define CP_WAIT2()        asm volatile("cp.async.wait_group 2;" ::: "memory")

__device__ __forceinline__ void ldsm4(uint32_t* r, uint32_t addr) {
    asm volatile("ldmatrix.sync.aligned.m8n8.x4.shared.b16 {%0,%1,%2,%3}, [%4];"
        : "=r"(r[0]), "=r"(r[1]), "=r"(r[2]), "=r"(r[3]) : "r"(addr));
}
__device__ __forceinline__ void mma16816h(float* d, const uint32_t* a, const uint32_t* b) {
    asm volatile("mma.sync.aligned.m16n8k16.row.col.f32.f16.f16.f32 "
        "{%0,%1,%2,%3}, {%4,%5,%6,%7}, {%8,%9}, {%0,%1,%2,%3};"
        : "+f"(d[0]), "+f"(d[1]), "+f"(d[2]), "+f"(d[3])
        : "r"(a[0]), "r"(a[1]), "r"(a[2]), "r"(a[3]), "r"(b[0]), "r"(b[1]));
}

// ---------------------------------------------------------------------------
// Kernel 0: weight prep.
// ---------------------------------------------------------------------------
__global__ void __launch_bounds__(256) prep_w_kernel(
    const float* __restrict__ wgi, const float* __restrict__ wpi,
    const float* __restrict__ wgo, const float* __restrict__ wpo)
{
    int idx = blockIdx.x*256 + threadIdx.x;   // 0..65535
    {
        int g = idx >> 14, rem = idx & 16383;
        int row = rem >> 7, k = rem & 127;
        int col = g*64 + (row >> 1);
        float v = (row & 1) ? wpi[k*256 + col] : wgi[k*256 + col];
        g_wcI[idx] = __float2half_rn(v);
    }
    if (idx < 16384) {
        int n = idx >> 7, k = idx & 127;
        g_wgo16[idx] = __float2half_rn(wgo[k*128 + n]);
        g_wpo16[idx] = __float2half_rn(wpo[k*128 + n]);
    }
}

// ---------------------------------------------------------------------------
// Kernel 1: proj7 — persistent; 64-token tiles; 5 weight chunks smem-resident;
// A hoisted to regs; x staged via cp.async (prefetch next during MMA);
// a/b written by DIRECT scalar-half stores (no transpose buffer, no syncs).
// ---------------------------------------------------------------------------
#define PROW   272
#define PTILE  (128*PROW)         // 34816
#define ATILE  (64*PROW)          // 17408
#define XROW   528
#define P7_A    0
#define P7_B    ATILE                      // 17408
#define P7_X    (P7_B + 5*PTILE)           // 191488
#define P7_SMEM (P7_X + 64*XROW)           // 225280
#define NP7     (NTOK/64)                  // 9216

__global__ void __launch_bounds__(256) proj7_kernel(
    const float* __restrict__ x, const float* __restrict__ mask,
    const float* __restrict__ nw, const float* __restrict__ nb)
{
    extern __shared__ char sm[];
    const uint32_t base = smem_u32(sm);
    const int tid = threadIdx.x;
    const int bid = blockIdx.x;

    const int wid  = tid >> 5;
    const int lane = tid & 31;
    const int m_base = (wid >> 2) * 32;
    const int n_base = (wid & 3) * 32;
    const int a_row  = lane & 15;
    const int a_half = lane >> 4;
    const int b_quad = lane >> 3;
    const int b_row  = (b_quad >> 1)*8 + (lane & 7);
    const int b_half = b_quad & 1;

    // --- load ALL 5 B chunks + first x tile ---
    const __half* csrc[5] = { g_wcI, g_wcI + 16384, g_wcI + 32768,
                              g_wcI + 49152, g_wgo16 };
    for (int cc = 0; cc < 5; cc++) {
        const __half* s = csrc[cc];
        uint32_t dst = base + P7_B + cc*PTILE;
        #pragma unroll
        for (int rep = 0; rep < 8; rep++) {
            int it = tid + rep*256;
            int row = it >> 4, q = it & 15;
            CP_ASYNC16(dst + row*PROW + q*16, (const char*)(s + row*128) + q*16);
        }
    }
    {
        int t0 = bid * 64;
        #pragma unroll
        for (int rep = 0; rep < 8; rep++) {
            int it = tid + rep*256;
            int row = it >> 5, q = it & 31;
            CP_ASYNC16(base + P7_X + row*XROW + q*16,
                       x + (size_t)(t0 + row)*CCH + q*4);
        }
    }
    CP_COMMIT();
    CP_WAIT0();
    __syncthreads();

    const float* xstg = (const float*)(sm + P7_X);
    const int tl = tid >> 2, qq = tid & 3;    // LN: 4 threads per token

    for (int tile = bid; tile < NP7; tile += NSM) {
        const int t0 = tile * 64;

        // --- LN from x staging -> fp16 A ---
        {
            float v[32];
            float s = 0.f;
            #pragma unroll
            for (int i = 0; i < 8; i++) {
                float4 f = *(const float4*)&xstg[tl*132 + qq*32 + i*4];
                v[i*4]=f.x; v[i*4+1]=f.y; v[i*4+2]=f.z; v[i*4+3]=f.w;
                s += f.x + f.y + f.z + f.w;
            }
            s += __shfl_xor_sync(0xFFFFFFFFu, s, 1);
            s += __shfl_xor_sync(0xFFFFFFFFu, s, 2);
            float m = s * (1.f/128.f);
            float q2 = 0.f;
            #pragma unroll
            for (int i = 0; i < 32; i++) { float d = v[i]-m; q2 += d*d; }
            q2 += __shfl_xor_sync(0xFFFFFFFFu, q2, 1);
            q2 += __shfl_xor_sync(0xFFFFFFFFu, q2, 2);
            float rs = rsqrtf(q2 * (1.f/128.f) + 1e-5f);

            #pragma unroll
            for (int i = 0; i < 16; i++) {
                int k = qq*32 + i*2;
                float v0 = (v[i*2]   - m)*rs*__ldg(&nw[k])   + __ldg(&nb[k]);
                float v1 = (v[i*2+1] - m)*rs*__ldg(&nw[k+1]) + __ldg(&nb[k+1]);
                __half2 hh;
                hh.x = __float2half_rn(v0);
                hh.y = __float2half_rn(v1);
                *(__half2*)(sm + P7_A + tl*PROW + k*2) = hh;
            }
        }
        __syncthreads();   // A visible; x staging consumed

        // --- prefetch next x tile (overlaps MMA) ---
        if (tile + NSM < NP7) {
            int nt0 = (tile + NSM) * 64;
            #pragma unroll
            for (int rep = 0; rep < 8; rep++) {
                int it = tid + rep*256;
                int row = it >> 5, q = it & 31;
                CP_ASYNC16(base + P7_X + row*XROW + q*16,
                           x + (size_t)(nt0 + row)*CCH + q*4);
            }
        }
        CP_COMMIT();

        // --- hoist A fragments to registers (once per tile) ---
        uint32_t Af[8][2][4];
        #pragma unroll
        for (int ks = 0; ks < 8; ks++) {
            const uint32_t koff = ks*32;
            #pragma unroll
            for (int mt = 0; mt < 2; mt++) {
                uint32_t r = (m_base + mt*16 + a_row)*PROW + koff + a_half*16;
                ldsm4(Af[ks][mt], base + P7_A + r);
            }
        }

        // --- 5 chunks, B resident, A in registers, direct-store epilogues ---
        #pragma unroll
        for (int c = 0; c < 5; c++) {
            const uint32_t sb = base + P7_B + c*PTILE;
            float acc[2][4][4];
            #pragma unroll
            for (int mt = 0; mt < 2; mt++)
                #pragma unroll
                for (int nt = 0; nt < 4; nt++)
                    #pragma unroll
                    for (int r = 0; r < 4; r++) acc[mt][nt][r] = 0.f;

            #pragma unroll
            for (int ks = 0; ks < 8; ks++) {
                const uint32_t koff = ks*32;
                uint32_t Bf[4][2];
                #pragma unroll
                for (int p = 0; p < 2; p++) {
                    uint32_t r = (n_base + p*16 + b_row)*PROW + koff + b_half*16;
                    uint32_t th[4];
                    ldsm4(th, sb + r);
                    Bf[2*p][0]   = th[0]; Bf[2*p][1]   = th[1];
                    Bf[2*p+1][0] = th[2]; Bf[2*p+1][1] = th[3];
                }
                #pragma unroll
                for (int mt = 0; mt < 2; mt++)
                    #pragma unroll
                    for (int nt = 0; nt < 4; nt++)
                        mma16816h(acc[mt][nt], Af[ks][mt], Bf[nt]);
            }

            if (c < 4) {
                // a/b epilogue: DIRECT scalar-half stores, channel-major
                const bool isA = (c < 2);
                const int cgl = (c & 1) * 64;
                __half* dst = isA ? g_ahi : g_bhi;
                #pragma unroll
                for (int mt = 0; mt < 2; mt++) {
                    #pragma unroll
                    for (int rp = 0; rp < 2; rp++) {
                        int t = t0 + m_base + mt*16 + rp*8 + (lane >> 2);
                        float mk = isA ? __ldg(&mask[t]) : 1.f;
                        #pragma unroll
                        for (int nt = 0; nt < 4; nt++) {
                            int cch = cgl + (n_base >> 1) + nt*4 + (lane & 3);
                            float val = sigmoidf_(acc[mt][nt][rp*2]) * acc[mt][nt][rp*2+1] * mk;
                            dst[(size_t)cch*NTOK + t] = __float2half_rn(val);
                        }
                    }
                }
            } else {
                // out-gate epilogue: token-major sigmoid -> fp16
                #pragma unroll
                for (int mt = 0; mt < 2; mt++) {
                    #pragma unroll
                    for (int rp = 0; rp < 2; rp++) {
                        int t = t0 + m_base + mt*16 + rp*8 + (lane >> 2);
                        #pragma unroll
                        for (int nt = 0; nt < 4; nt++) {
                            int ch = n_base + nt*8 + (lane & 3)*2;
                            __half2 f;
                            f.x = __float2half_rn(sigmoidf_(acc[mt][nt][rp*2]));
                            f.y = __float2half_rn(sigmoidf_(acc[mt][nt][rp*2+1]));
                            *(__half2*)&g_gate16[(size_t)t*CCH + ch] = f;
                        }
                    }
                }
            }
        }

        // x staging must be filled before next LN: wait + barrier
        CP_WAIT0();
        __syncthreads();
    }
}

// ---------------------------------------------------------------------------
// Kernel 2: tri einsum, single-pass fp16, K-chunk=128, triple buf, fp16 out.
// ---------------------------------------------------------------------------
#define TILE2   (128*PROW)          // 34816
#define CHUNKT  (2*TILE2)           // 69632
#define TRI_SMEM (3*CHUNKT)         // 208896

__device__ __forceinline__ void tri_load_chunk(
    uint32_t sbuf, const __half* sA, const __half* sB, int kk, int tid)
{
    const __half* srcs[2] = {sA, sB};
    #pragma unroll
    for (int rep = 0; rep < 16; rep++) {
        int it   = tid + rep*256;             // 0..4095
        int tile = it >> 11;
        int row  = (it >> 4) & 127;
        int q    = it & 15;
        const __half* gp = srcs[tile] + (size_t)row*SDIM + kk + q*8;
        CP_ASYNC16(sbuf + tile*TILE2 + row*PROW + q*16, gp);
    }
}

__global__ void __launch_bounds__(256) tri_mma_kernel()
{
    extern __shared__ char dynsm[];
    const uint32_t base = smem_u32(dynsm);

    const int tid  = threadIdx.x;
    const int wid  = tid >> 5;
    const int lane = tid & 31;
    const int m_base = (wid >> 2) * 64;
    const int n_base = (wid & 3) * 32;

    const int c  = blockIdx.y;
    const int i0 = (blockIdx.x / 6) * 128;
    const int j0 = (blockIdx.x % 6) * 128;

    const __half* sAh = g_ahi + (size_t)c*NTOK + (size_t)i0*SDIM;
    const __half* sBh = g_bhi + (size_t)c*NTOK + (size_t)j0*SDIM;

    float acc[4][4][4];
    #pragma unroll
    for (int mt = 0; mt < 4; mt++)
        #pragma unroll
        for (int nt = 0; nt < 4; nt++)
            #pragma unroll
            for (int r = 0; r < 4; r++) acc[mt][nt][r] = 0.f;

    const int a_row  = lane & 15;
    const int a_half = lane >> 4;
    const int b_quad = lane >> 3;
    const int b_row  = (b_quad >> 1) * 8 + (lane & 7);
    const int b_half = b_quad & 1;

    tri_load_chunk(base + 0*CHUNKT, sAh, sBh, 0,   tid); CP_COMMIT();
    tri_load_chunk(base + 1*CHUNKT, sAh, sBh, 128, tid); CP_COMMIT();

    for (int n = 0; n < 6; n++) {
        if (n + 2 < 6)
            tri_load_chunk(base + ((n+2)%3)*CHUNKT, sAh, sBh, (n+2)*128, tid);
        CP_COMMIT();
        CP_WAIT2();
        __syncthreads();

        const uint32_t sb = base + (n%3)*CHUNKT;
        #pragma unroll
        for (int ks = 0; ks < 8; ks++) {
            uint32_t Ah[4][4], Bh[4][2];
            const uint32_t koff = ks*32;
            #pragma unroll
            for (int mt = 0; mt < 4; mt++) {
                uint32_t r = (m_base + mt*16 + a_row)*PROW + koff + a_half*16;
                ldsm4(Ah[mt], sb + r);
            }
            #pragma unroll
            for (int p = 0; p < 2; p++) {
                uint32_t r = (n_base + p*16 + b_row)*PROW + koff + b_half*16;
                uint32_t th[4];
                ldsm4(th, sb + TILE2 + r);
                Bh[2*p][0]   = th[0]; Bh[2*p][1]   = th[1];
                Bh[2*p+1][0] = th[2]; Bh[2*p+1][1] = th[3];
            }
            #pragma unroll
            for (int mt = 0; mt < 4; mt++)
                #pragma unroll
                for (int nt = 0; nt < 4; nt++)
                    mma16816h(acc[mt][nt], Ah[mt], Bh[nt]);
        }
        __syncthreads();
    }

    __half* T = g_tri16 + (size_t)c*NTOK;
    const int er = i0 + m_base + (lane >> 2);
    const int ec2 = j0 + n_base + (lane & 3)*2;
    #pragma unroll
    for (int mt = 0; mt < 4; mt++) {
        #pragma unroll
        for (int nt = 0; nt < 4; nt++) {
            int rr = er + mt*16;
            int cc = ec2 + nt*8;
            __half2 v0; v0.x = __float2half_rn(acc[mt][nt][0]);
                        v0.y = __float2half_rn(acc[mt][nt][1]);
            __half2 v1; v1.x = __float2half_rn(acc[mt][nt][2]);
                        v1.y = __float2half_rn(acc[mt][nt][3]);
            *(__half2*)&T[(size_t)rr*SDIM + cc]     = v0;
            *(__half2*)&T[(size_t)(rr+8)*SDIM + cc] = v1;
        }
    }
}

// ---------------------------------------------------------------------------
// Kernel 3: out2 — persistent, 256 thr, 64-token tiles, 2 CTAs/SM. (R13 exact)
// ---------------------------------------------------------------------------
#define TROW     144                    // 64 tok * 2B + 16 pad
#define O2_TRI   0                      // 128 ch x 144B = 18432
#define O2_A     18432                  // 64 x 272 = 17408
#define O2_B     (O2_A + ATILE)         // 35840
#define O2_SMEM  (O2_B + PTILE)         // 70656  (2 CTAs/SM)
#define NOT64    (NTOK/64)              // 9216
#define OGRID    (2*NSM)                // 296

__global__ void __launch_bounds__(256) out2_kernel(
    const float* __restrict__ now, const float* __restrict__ nob,
    float* __restrict__ out)
{
    extern __shared__ char sm[];
    const uint32_t base = smem_u32(sm);
    const int tid = threadIdx.x;
    const int bid = blockIdx.x;

    // one-time B (wpo^T fp16)
    #pragma unroll
    for (int rep = 0; rep < 8; rep++) {
        int it = tid + rep*256;
        int row = it >> 4, q = it & 15;
        CP_ASYNC16(base + O2_B + row*PROW + q*16,
                   (const char*)(g_wpo16 + row*128) + q*16);
    }
    // first tri tile (fp16, 64 tokens)
    {
        int t0 = bid * 64;
        #pragma unroll
        for (int rep = 0; rep < 4; rep++) {
            int it = tid + rep*256;           // 0..1023
            int ch = it >> 3, q = it & 7;
            CP_ASYNC16(base + O2_TRI + ch*TROW + q*16,
                       g_tri16 + (size_t)ch*NTOK + t0 + q*8);
        }
    }
    CP_COMMIT();

    const int wid  = tid >> 5;
    const int lane = tid & 31;
    const int m_base = (wid >> 2) * 32;
    const int n_base = (wid & 3) * 32;
    const int a_row  = lane & 15;
    const int a_half = lane >> 4;
    const int b_quad = lane >> 3;
    const int b_row  = (b_quad >> 1)*8 + (lane & 7);
    const int b_half = b_quad & 1;
    const int er = m_base + (lane >> 2);
    const int ec = n_base + (lane & 3)*2;

    const __half* trs = (const __half*)(sm + O2_TRI);
    const int tl = tid >> 2, qq = tid & 3;

    for (int tile = bid; tile < NOT64; tile += OGRID) {
        const int t0 = tile * 64;
        CP_WAIT0();
        __syncthreads();

        // LN over channels (fp16 staging) -> fp16 A [t][ch]
        {
            float s = 0.f;
            float vch[32];
            #pragma unroll
            for (int j = 0; j < 32; j++) {
                vch[j] = __half2float(trs[(qq*32 + j)*72 + tl]);
                s += vch[j];
            }
            s += __shfl_xor_sync(0xFFFFFFFFu, s, 1);
            s += __shfl_xor_sync(0xFFFFFFFFu, s, 2);
            float m = s * (1.f/128.f);
            float q2 = 0.f;
            #pragma unroll
            for (int j = 0; j < 32; j++) {
                float d = vch[j] - m;
                q2 += d*d;
            }
            q2 += __shfl_xor_sync(0xFFFFFFFFu, q2, 1);
            q2 += __shfl_xor_sync(0xFFFFFFFFu, q2, 2);
            float rs = rsqrtf(q2 * (1.f/128.f) + 1e-5f);

            #pragma unroll
            for (int j = 0; j < 16; j++) {
                int ch = qq*32 + j*2;
                float v0 = (vch[j*2]   - m)*rs*__ldg(&now[ch])   + __ldg(&nob[ch]);
                float v1 = (vch[j*2+1] - m)*rs*__ldg(&now[ch+1]) + __ldg(&nob[ch+1]);
                __half2 hh;
                hh.x = __float2half_rn(v0);
                hh.y = __float2half_rn(v1);
                *(__half2*)(sm + O2_A + tl*PROW + ch*2) = hh;
            }
        }
        __syncthreads();

        // prefetch next tri tile into staging
        if (tile + OGRID < NOT64) {
            int nt0 = (tile + OGRID) * 64;
            #pragma unroll
            for (int rep = 0; rep < 4; rep++) {
                int it = tid + rep*256;
                int ch = it >> 3, q = it & 7;
                CP_ASYNC16(base + O2_TRI + ch*TROW + q*16,
                           g_tri16 + (size_t)ch*NTOK + nt0 + q*8);
            }
        }
        CP_COMMIT();

        float acc[2][4][4];
        #pragma unroll
        for (int mt = 0; mt < 2; mt++)
            #pragma unroll
            for (int nt = 0; nt < 4; nt++)
                #pragma unroll
                for (int r = 0; r < 4; r++) acc[mt][nt][r] = 0.f;

        #pragma unroll
        for (int ks = 0; ks < 8; ks++) {
            const uint32_t koff = ks*32;
            uint32_t Ah[2][4];
            #pragma unroll
            for (int mt = 0; mt < 2; mt++) {
                uint32_t r = (m_base + mt*16 + a_row)*PROW + koff + a_half*16;
                ldsm4(Ah[mt], base + O2_A + r);
            }
            uint32_t Bf[4][2];
            #pragma unroll
            for (int p = 0; p < 2; p++) {
                uint32_t r = (n_base + p*16 + b_row)*PROW + koff + b_half*16;
                uint32_t th[4];
                ldsm4(th, base + O2_B + r);
                Bf[2*p][0]   = th[0]; Bf[2*p][1]   = th[1];
                Bf[2*p+1][0] = th[2]; Bf[2*p+1][1] = th[3];
            }
            #pragma unroll
            for (int mt = 0; mt < 2; mt++)
                #pragma unroll
                for (int nt = 0; nt < 4; nt++) mma16816h(acc[mt][nt], Ah[mt], Bf[nt]);
        }

        // epilogue: gate fp16 via direct LDG, out stores
        #pragma unroll
        for (int mt = 0; mt < 2; mt++) {
            #pragma unroll
            for (int rp = 0; rp < 2; rp++) {
                int t = t0 + er + mt*16 + rp*8;
                #pragma unroll
                for (int nt = 0; nt < 4; nt++) {
                    int cc = ec + nt*8;
                    __half2 gh = __ldg((const __half2*)&g_gate16[(size_t)t*CCH + cc]);
                    float2 o = make_float2(acc[mt][nt][rp*2]   * __half2float(gh.x),
                                           acc[mt][nt][rp*2+1] * __half2float(gh.y));
                    *(float2*)&out[(size_t)t*CCH + cc] = o;
                }
            }
        }
        __syncthreads();
    }
}

// ---------------------------------------------------------------------------
extern "C" void kernel_launch(void* const* d_in, const int* in_sizes, int n_in,
                              void* d_out, int out_size)
{
    const float* x    = (const float*)d_in[0];
    const float* mask = (const float*)d_in[1];
    const float* niw  = (const float*)d_in[2];
    const float* nib  = (const float*)d_in[3];
    const float* wgi  = (const float*)d_in[4];
    const float* wpi  = (const float*)d_in[5];
    const float* now  = (const float*)d_in[6];
    const float* nob  = (const float*)d_in[7];
    const float* wgo  = (const float*)d_in[8];
    const float* wpo  = (const float*)d_in[9];
    float* out = (float*)d_out;

    cudaFuncSetAttribute(proj7_kernel,
        cudaFuncAttributeMaxDynamicSharedMemorySize, P7_SMEM);
    cudaFuncSetAttribute(tri_mma_kernel,
        cudaFuncAttributeMaxDynamicSharedMemorySize, TRI_SMEM);
    cudaFuncSetAttribute(out2_kernel,
        cudaFuncAttributeMaxDynamicSharedMemorySize, O2_SMEM);

    prep_w_kernel<<<256, 256>>>(wgi, wpi, wgo, wpo);
    proj7_kernel<<<NSM, 256, P7_SMEM>>>(x, mask, niw, nib);
    tri_mma_kernel<<<dim3(36, 128), 256, TRI_SMEM>>>();
    out2_kernel<<<OGRID, 256, O2_SMEM>>>(now, nob, out);
}

// round 15
// speedup vs baseline: 1.8097x; 1.0348x over previous
#include <cuda_runtime.h>
#include <cuda_bf16.h>
#include <cuda_fp16.h>
#include <math.h>
#include <stdint.h>

#define SDIM 768
#define CCH  128
#define NTOK (SDIM*SDIM)        // 589824 tokens
#define SELEM 75497472          // 128 * 589824
#define NSM   148

// Scratch: a, b, tri, gate all fp16
__device__ __half g_ahi[SELEM];
__device__ __half g_bhi[SELEM];
__device__ __half g_tri16[SELEM];
__device__ __half g_gate16[SELEM];

// Prepped fp16 weights:
// g_wcI: 4 groups x 128 rows x 128 k; group g row 2r = wgi col(64g+r), row 2r+1 = wpi col(64g+r)
__device__ __half g_wcI[4*128*128];
__device__ __half g_wgo16[128*128];   // wgo^T [n][k]
__device__ __half g_wpo16[128*128];   // wpo^T [co][h]

__device__ __forceinline__ float sigmoidf_(float v) {
    return 1.f / (1.f + __expf(-v));
}
__device__ __forceinline__ uint32_t smem_u32(const void* p) {
    uint32_t a;
    asm("{ .reg .u64 t; cvta.to.shared.u64 t, %1; cvt.u32.u64 %0, t; }"
        : "=r"(a) : "l"(p));
    return a;
}
#define CP_ASYNC16(d, s)  asm volatile("cp.async.cg.shared.global [%0], [%1], 16;" :: "r"(d), "l"(s))
#define CP_COMMIT()       asm volatile("cp.async.commit_group;" ::: "memory")
#define CP_WAIT0()        asm volatile("cp.async.wait_group 0;" ::: "memory")
#define CP_WAIT1()        asm volatile("cp.async.wait_group 1;" ::: "memory")

__device__ __forceinline__ void ldsm4(uint32_t* r, uint32_t addr) {
    asm volatile("ldmatrix.sync.aligned.m8n8.x4.shared.b16 {%0,%1,%2,%3}, [%4];"
        : "=r"(r[0]), "=r"(r[1]), "=r"(r[2]), "=r"(r[3]) : "r"(addr));
}
__device__ __forceinline__ void mma16816h(float* d, const uint32_t* a, const uint32_t* b) {
    asm volatile("mma.sync.aligned.m16n8k16.row.col.f32.f16.f16.f32 "
        "{%0,%1,%2,%3}, {%4,%5,%6,%7}, {%8,%9}, {%0,%1,%2,%3};"
        : "+f"(d[0]), "+f"(d[1]), "+f"(d[2]), "+f"(d[3])
        : "r"(a[0]), "r"(a[1]), "r"(a[2]), "r"(a[3]), "r"(b[0]), "r"(b[1]));
}

// ---------------------------------------------------------------------------
// Kernel 0: weight prep.
// ---------------------------------------------------------------------------
__global__ void __launch_bounds__(256) prep_w_kernel(
    const float* __restrict__ wgi, const float* __restrict__ wpi,
    const float* __restrict__ wgo, const float* __restrict__ wpo)
{
    int idx = blockIdx.x*256 + threadIdx.x;   // 0..65535
    {
        int g = idx >> 14, rem = idx & 16383;
        int row = rem >> 7, k = rem & 127;
        int col = g*64 + (row >> 1);
        float v = (row & 1) ? wpi[k*256 + col] : wgi[k*256 + col];
        g_wcI[idx] = __float2half_rn(v);
    }
    if (idx < 16384) {
        int n = idx >> 7, k = idx & 127;
        g_wgo16[idx] = __float2half_rn(wgo[k*128 + n]);
        g_wpo16[idx] = __float2half_rn(wpo[k*128 + n]);
    }
}

// ---------------------------------------------------------------------------
// Kernel 1: proj7 — persistent; 64-token tiles; B resident; A hoisted;
// direct-store epilogues. (R14 exact)
// ---------------------------------------------------------------------------
#define PROW   272
#define PTILE  (128*PROW)         // 34816
#define ATILE  (64*PROW)          // 17408
#define XROW   528
#define P7_A    0
#define P7_B    ATILE                      // 17408
#define P7_X    (P7_B + 5*PTILE)           // 191488
#define P7_SMEM (P7_X + 64*XROW)           // 225280
#define NP7     (NTOK/64)                  // 9216

__global__ void __launch_bounds__(256) proj7_kernel(
    const float* __restrict__ x, const float* __restrict__ mask,
    const float* __restrict__ nw, const float* __restrict__ nb)
{
    extern __shared__ char sm[];
    const uint32_t base = smem_u32(sm);
    const int tid = threadIdx.x;
    const int bid = blockIdx.x;

    const int wid  = tid >> 5;
    const int lane = tid & 31;
    const int m_base = (wid >> 2) * 32;
    const int n_base = (wid & 3) * 32;
    const int a_row  = lane & 15;
    const int a_half = lane >> 4;
    const int b_quad = lane >> 3;
    const int b_row  = (b_quad >> 1)*8 + (lane & 7);
    const int b_half = b_quad & 1;

    const __half* csrc[5] = { g_wcI, g_wcI + 16384, g_wcI + 32768,
                              g_wcI + 49152, g_wgo16 };
    for (int cc = 0; cc < 5; cc++) {
        const __half* s = csrc[cc];
        uint32_t dst = base + P7_B + cc*PTILE;
        #pragma unroll
        for (int rep = 0; rep < 8; rep++) {
            int it = tid + rep*256;
            int row = it >> 4, q = it & 15;
            CP_ASYNC16(dst + row*PROW + q*16, (const char*)(s + row*128) + q*16);
        }
    }
    {
        int t0 = bid * 64;
        #pragma unroll
        for (int rep = 0; rep < 8; rep++) {
            int it = tid + rep*256;
            int row = it >> 5, q = it & 31;
            CP_ASYNC16(base + P7_X + row*XROW + q*16,
                       x + (size_t)(t0 + row)*CCH + q*4);
        }
    }
    CP_COMMIT();
    CP_WAIT0();
    __syncthreads();

    const float* xstg = (const float*)(sm + P7_X);
    const int tl = tid >> 2, qq = tid & 3;

    for (int tile = bid; tile < NP7; tile += NSM) {
        const int t0 = tile * 64;

        {
            float v[32];
            float s = 0.f;
            #pragma unroll
            for (int i = 0; i < 8; i++) {
                float4 f = *(const float4*)&xstg[tl*132 + qq*32 + i*4];
                v[i*4]=f.x; v[i*4+1]=f.y; v[i*4+2]=f.z; v[i*4+3]=f.w;
                s += f.x + f.y + f.z + f.w;
            }
            s += __shfl_xor_sync(0xFFFFFFFFu, s, 1);
            s += __shfl_xor_sync(0xFFFFFFFFu, s, 2);
            float m = s * (1.f/128.f);
            float q2 = 0.f;
            #pragma unroll
            for (int i = 0; i < 32; i++) { float d = v[i]-m; q2 += d*d; }
            q2 += __shfl_xor_sync(0xFFFFFFFFu, q2, 1);
            q2 += __shfl_xor_sync(0xFFFFFFFFu, q2, 2);
            float rs = rsqrtf(q2 * (1.f/128.f) + 1e-5f);

            #pragma unroll
            for (int i = 0; i < 16; i++) {
                int k = qq*32 + i*2;
                float v0 = (v[i*2]   - m)*rs*__ldg(&nw[k])   + __ldg(&nb[k]);
                float v1 = (v[i*2+1] - m)*rs*__ldg(&nw[k+1]) + __ldg(&nb[k+1]);
                __half2 hh;
                hh.x = __float2half_rn(v0);
                hh.y = __float2half_rn(v1);
                *(__half2*)(sm + P7_A + tl*PROW + k*2) = hh;
            }
        }
        __syncthreads();

        if (tile + NSM < NP7) {
            int nt0 = (tile + NSM) * 64;
            #pragma unroll
            for (int rep = 0; rep < 8; rep++) {
                int it = tid + rep*256;
                int row = it >> 5, q = it & 31;
                CP_ASYNC16(base + P7_X + row*XROW + q*16,
                           x + (size_t)(nt0 + row)*CCH + q*4);
            }
        }
        CP_COMMIT();

        uint32_t Af[8][2][4];
        #pragma unroll
        for (int ks = 0; ks < 8; ks++) {
            const uint32_t koff = ks*32;
            #pragma unroll
            for (int mt = 0; mt < 2; mt++) {
                uint32_t r = (m_base + mt*16 + a_row)*PROW + koff + a_half*16;
                ldsm4(Af[ks][mt], base + P7_A + r);
            }
        }

        #pragma unroll
        for (int c = 0; c < 5; c++) {
            const uint32_t sb = base + P7_B + c*PTILE;
            float acc[2][4][4];
            #pragma unroll
            for (int mt = 0; mt < 2; mt++)
                #pragma unroll
                for (int nt = 0; nt < 4; nt++)
                    #pragma unroll
                    for (int r = 0; r < 4; r++) acc[mt][nt][r] = 0.f;

            #pragma unroll
            for (int ks = 0; ks < 8; ks++) {
                const uint32_t koff = ks*32;
                uint32_t Bf[4][2];
                #pragma unroll
                for (int p = 0; p < 2; p++) {
                    uint32_t r = (n_base + p*16 + b_row)*PROW + koff + b_half*16;
                    uint32_t th[4];
                    ldsm4(th, sb + r);
                    Bf[2*p][0]   = th[0]; Bf[2*p][1]   = th[1];
                    Bf[2*p+1][0] = th[2]; Bf[2*p+1][1] = th[3];
                }
                #pragma unroll
                for (int mt = 0; mt < 2; mt++)
                    #pragma unroll
                    for (int nt = 0; nt < 4; nt++)
                        mma16816h(acc[mt][nt], Af[ks][mt], Bf[nt]);
            }

            if (c < 4) {
                const bool isA = (c < 2);
                const int cgl = (c & 1) * 64;
                __half* dst = isA ? g_ahi : g_bhi;
                #pragma unroll
                for (int mt = 0; mt < 2; mt++) {
                    #pragma unroll
                    for (int rp = 0; rp < 2; rp++) {
                        int t = t0 + m_base + mt*16 + rp*8 + (lane >> 2);
                        float mk = isA ? __ldg(&mask[t]) : 1.f;
                        #pragma unroll
                        for (int nt = 0; nt < 4; nt++) {
                            int cch = cgl + (n_base >> 1) + nt*4 + (lane & 3);
                            float val = sigmoidf_(acc[mt][nt][rp*2]) * acc[mt][nt][rp*2+1] * mk;
                            dst[(size_t)cch*NTOK + t] = __float2half_rn(val);
                        }
                    }
                }
            } else {
                #pragma unroll
                for (int mt = 0; mt < 2; mt++) {
                    #pragma unroll
                    for (int rp = 0; rp < 2; rp++) {
                        int t = t0 + m_base + mt*16 + rp*8 + (lane >> 2);
                        #pragma unroll
                        for (int nt = 0; nt < 4; nt++) {
                            int ch = n_base + nt*8 + (lane & 3)*2;
                            __half2 f;
                            f.x = __float2half_rn(sigmoidf_(acc[mt][nt][rp*2]));
                            f.y = __float2half_rn(sigmoidf_(acc[mt][nt][rp*2+1]));
                            *(__half2*)&g_gate16[(size_t)t*CCH + ch] = f;
                        }
                    }
                }
            }
        }

        CP_WAIT0();
        __syncthreads();
    }
}

// ---------------------------------------------------------------------------
// Kernel 2: tri2 — 256x128 output tile, K-chunk=128, double-buffered.
// 8 warps as 4m x 2n (warp tile 64x64). Grid (18, 128) = 2304 CTAs.
// ---------------------------------------------------------------------------
#define TA_TILE  (256*PROW)          // 69632
#define TB_TILE  (128*PROW)          // 34816
#define TCHUNK   (TA_TILE + TB_TILE) // 104448
#define TRI_SMEM (2*TCHUNK)          // 208896

__device__ __forceinline__ void tri2_load_chunk(
    uint32_t sbuf, const __half* sA, const __half* sB, int kk, int tid)
{
    // A: 256 rows (4096 ops), B: 128 rows (2048 ops) -> 24 reps x 256 thr
    #pragma unroll
    for (int rep = 0; rep < 16; rep++) {
        int it  = tid + rep*256;              // 0..4095
        int row = it >> 4, q = it & 15;
        CP_ASYNC16(sbuf + row*PROW + q*16, sA + (size_t)row*SDIM + kk + q*8);
    }
    #pragma unroll
    for (int rep = 0; rep < 8; rep++) {
        int it  = tid + rep*256;              // 0..2047
        int row = it >> 4, q = it & 15;
        CP_ASYNC16(sbuf + TA_TILE + row*PROW + q*16,
                   sB + (size_t)row*SDIM + kk + q*8);
    }
}

__global__ void __launch_bounds__(256) tri_mma_kernel()
{
    extern __shared__ char dynsm[];
    const uint32_t base = smem_u32(dynsm);

    const int tid  = threadIdx.x;
    const int wid  = tid >> 5;
    const int lane = tid & 31;
    const int m_base = (wid >> 1) * 64;   // 4 m-warps
    const int n_base = (wid & 1) * 64;    // 2 n-warps

    const int c  = blockIdx.y;
    const int i0 = (blockIdx.x / 6) * 256;
    const int j0 = (blockIdx.x % 6) * 128;

    const __half* sAh = g_ahi + (size_t)c*NTOK + (size_t)i0*SDIM;
    const __half* sBh = g_bhi + (size_t)c*NTOK + (size_t)j0*SDIM;

    float acc[4][8][4];
    #pragma unroll
    for (int mt = 0; mt < 4; mt++)
        #pragma unroll
        for (int nt = 0; nt < 8; nt++)
            #pragma unroll
            for (int r = 0; r < 4; r++) acc[mt][nt][r] = 0.f;

    const int a_row  = lane & 15;
    const int a_half = lane >> 4;
    const int b_quad = lane >> 3;
    const int b_row  = (b_quad >> 1) * 8 + (lane & 7);
    const int b_half = b_quad & 1;

    tri2_load_chunk(base, sAh, sBh, 0, tid); CP_COMMIT();

    for (int n = 0; n < 6; n++) {
        if (n + 1 < 6) {
            tri2_load_chunk(base + ((n+1)&1)*TCHUNK, sAh, sBh, (n+1)*128, tid);
            CP_COMMIT();
            CP_WAIT1();
        } else {
            CP_WAIT0();
        }
        __syncthreads();

        const uint32_t sb = base + (n&1)*TCHUNK;
        #pragma unroll
        for (int ks = 0; ks < 8; ks++) {
            uint32_t Ah[4][4], Bh[8][2];
            const uint32_t koff = ks*32;
            #pragma unroll
            for (int mt = 0; mt < 4; mt++) {
                uint32_t r = (m_base + mt*16 + a_row)*PROW + koff + a_half*16;
                ldsm4(Ah[mt], sb + r);
            }
            #pragma unroll
            for (int p = 0; p < 4; p++) {
                uint32_t r = (n_base + p*16 + b_row)*PROW + koff + b_half*16;
                uint32_t th[4];
                ldsm4(th, sb + TA_TILE + r);
                Bh[2*p][0]   = th[0]; Bh[2*p][1]   = th[1];
                Bh[2*p+1][0] = th[2]; Bh[2*p+1][1] = th[3];
            }
            #pragma unroll
            for (int mt = 0; mt < 4; mt++)
                #pragma unroll
                for (int nt = 0; nt < 8; nt++)
                    mma16816h(acc[mt][nt], Ah[mt], Bh[nt]);
        }
        __syncthreads();
    }

    __half* T = g_tri16 + (size_t)c*NTOK;
    const int er = i0 + m_base + (lane >> 2);
    const int ec2 = j0 + n_base + (lane & 3)*2;
    #pragma unroll
    for (int mt = 0; mt < 4; mt++) {
        #pragma unroll
        for (int nt = 0; nt < 8; nt++) {
            int rr = er + mt*16;
            int cc = ec2 + nt*8;
            __half2 v0; v0.x = __float2half_rn(acc[mt][nt][0]);
                        v0.y = __float2half_rn(acc[mt][nt][1]);
            __half2 v1; v1.x = __float2half_rn(acc[mt][nt][2]);
                        v1.y = __float2half_rn(acc[mt][nt][3]);
            *(__half2*)&T[(size_t)rr*SDIM + cc]     = v0;
            *(__half2*)&T[(size_t)(rr+8)*SDIM + cc] = v1;
        }
    }
}

// ---------------------------------------------------------------------------
// Kernel 3: out2 — persistent, 256 thr, 64-token tiles, 2 CTAs/SM. (R14 exact)
// ---------------------------------------------------------------------------
#define TROW     144                    // 64 tok * 2B + 16 pad
#define O2_TRI   0                      // 128 ch x 144B = 18432
#define O2_A     18432                  // 64 x 272 = 17408
#define O2_B     (O2_A + ATILE)         // 35840
#define O2_SMEM  (O2_B + PTILE)         // 70656  (2 CTAs/SM)
#define NOT64    (NTOK/64)              // 9216
#define OGRID    (2*NSM)                // 296

__global__ void __launch_bounds__(256) out2_kernel(
    const float* __restrict__ now, const float* __restrict__ nob,
    float* __restrict__ out)
{
    extern __shared__ char sm[];
    const uint32_t base = smem_u32(sm);
    const int tid = threadIdx.x;
    const int bid = blockIdx.x;

    #pragma unroll
    for (int rep = 0; rep < 8; rep++) {
        int it = tid + rep*256;
        int row = it >> 4, q = it & 15;
        CP_ASYNC16(base + O2_B + row*PROW + q*16,
                   (const char*)(g_wpo16 + row*128) + q*16);
    }
    {
        int t0 = bid * 64;
        #pragma unroll
        for (int rep = 0; rep < 4; rep++) {
            int it = tid + rep*256;
            int ch = it >> 3, q = it & 7;
            CP_ASYNC16(base + O2_TRI + ch*TROW + q*16,
                       g_tri16 + (size_t)ch*NTOK + t0 + q*8);
        }
    }
    CP_COMMIT();

    const int wid  = tid >> 5;
    const int lane = tid & 31;
    const int m_base = (wid >> 2) * 32;
    const int n_base = (wid & 3) * 32;
    const int a_row  = lane & 15;
    const int a_half = lane >> 4;
    const int b_quad = lane >> 3;
    const int b_row  = (b_quad >> 1)*8 + (lane & 7);
    const int b_half = b_quad & 1;
    const int er = m_base + (lane >> 2);
    const int ec = n_base + (lane & 3)*2;

    const __half* trs = (const __half*)(sm + O2_TRI);
    const int tl = tid >> 2, qq = tid & 3;

    for (int tile = bid; tile < NOT64; tile += OGRID) {
        const int t0 = tile * 64;
        CP_WAIT0();
        __syncthreads();

        {
            float s = 0.f;
            float vch[32];
            #pragma unroll
            for (int j = 0; j < 32; j++) {
                vch[j] = __half2float(trs[(qq*32 + j)*72 + tl]);
                s += vch[j];
            }
            s += __shfl_xor_sync(0xFFFFFFFFu, s, 1);
            s += __shfl_xor_sync(0xFFFFFFFFu, s, 2);
            float m = s * (1.f/128.f);
            float q2 = 0.f;
            #pragma unroll
            for (int j = 0; j < 32; j++) {
                float d = vch[j] - m;
                q2 += d*d;
            }
            q2 += __shfl_xor_sync(0xFFFFFFFFu, q2, 1);
            q2 += __shfl_xor_sync(0xFFFFFFFFu, q2, 2);
            float rs = rsqrtf(q2 * (1.f/128.f) + 1e-5f);

            #pragma unroll
            for (int j = 0; j < 16; j++) {
                int ch = qq*32 + j*2;
                float v0 = (vch[j*2]   - m)*rs*__ldg(&now[ch])   + __ldg(&nob[ch]);
                float v1 = (vch[j*2+1] - m)*rs*__ldg(&now[ch+1]) + __ldg(&nob[ch+1]);
                __half2 hh;
                hh.x = __float2half_rn(v0);
                hh.y = __float2half_rn(v1);
                *(__half2*)(sm + O2_A + tl*PROW + ch*2) = hh;
            }
        }
        __syncthreads();

        if (tile + OGRID < NOT64) {
            int nt0 = (tile + OGRID) * 64;
            #pragma unroll
            for (int rep = 0; rep < 4; rep++) {
                int it = tid + rep*256;
                int ch = it >> 3, q = it & 7;
                CP_ASYNC16(base + O2_TRI + ch*TROW + q*16,
                           g_tri16 + (size_t)ch*NTOK + nt0 + q*8);
            }
        }
        CP_COMMIT();

        float acc[2][4][4];
        #pragma unroll
        for (int mt = 0; mt < 2; mt++)
            #pragma unroll
            for (int nt = 0; nt < 4; nt++)
                #pragma unroll
                for (int r = 0; r < 4; r++) acc[mt][nt][r] = 0.f;

        #pragma unroll
        for (int ks = 0; ks < 8; ks++) {
            const uint32_t koff = ks*32;
            uint32_t Ah[2][4];
            #pragma unroll
            for (int mt = 0; mt < 2; mt++) {
                uint32_t r = (m_base + mt*16 + a_row)*PROW + koff + a_half*16;
                ldsm4(Ah[mt], base + O2_A + r);
            }
            uint32_t Bf[4][2];
            #pragma unroll
            for (int p = 0; p < 2; p++) {
                uint32_t r = (n_base + p*16 + b_row)*PROW + koff + b_half*16;
                uint32_t th[4];
                ldsm4(th, base + O2_B + r);
                Bf[2*p][0]   = th[0]; Bf[2*p][1]   = th[1];
                Bf[2*p+1][0] = th[2]; Bf[2*p+1][1] = th[3];
            }
            #pragma unroll
            for (int mt = 0; mt < 2; mt++)
                #pragma unroll
                for (int nt = 0; nt < 4; nt++) mma16816h(acc[mt][nt], Ah[mt], Bf[nt]);
        }

        #pragma unroll
        for (int mt = 0; mt < 2; mt++) {
            #pragma unroll
            for (int rp = 0; rp < 2; rp++) {
                int t = t0 + er + mt*16 + rp*8;
                #pragma unroll
                for (int nt = 0; nt < 4; nt++) {
                    int cc = ec + nt*8;
                    __half2 gh = __ldg((const __half2*)&g_gate16[(size_t)t*CCH + cc]);
                    float2 o = make_float2(acc[mt][nt][rp*2]   * __half2float(gh.x),
                                           acc[mt][nt][rp*2+1] * __half2float(gh.y));
                    *(float2*)&out[(size_t)t*CCH + cc] = o;
                }
            }
        }
        __syncthreads();
    }
}

// ---------------------------------------------------------------------------
extern "C" void kernel_launch(void* const* d_in, const int* in_sizes, int n_in,
                              void* d_out, int out_size)
{
    const float* x    = (const float*)d_in[0];
    const float* mask = (const float*)d_in[1];
    const float* niw  = (const float*)d_in[2];
    const float* nib  = (const float*)d_in[3];
    const float* wgi  = (const float*)d_in[4];
    const float* wpi  = (const float*)d_in[5];
    const float* now  = (const float*)d_in[6];
    const float* nob  = (const float*)d_in[7];
    const float* wgo  = (const float*)d_in[8];
    const float* wpo  = (const float*)d_in[9];
    float* out = (float*)d_out;

    cudaFuncSetAttribute(proj7_kernel,
        cudaFuncAttributeMaxDynamicSharedMemorySize, P7_SMEM);
    cudaFuncSetAttribute(tri_mma_kernel,
        cudaFuncAttributeMaxDynamicSharedMemorySize, TRI_SMEM);
    cudaFuncSetAttribute(out2_kernel,
        cudaFuncAttributeMaxDynamicSharedMemorySize, O2_SMEM);

    prep_w_kernel<<<256, 256>>>(wgi, wpi, wgo, wpo);
    proj7_kernel<<<NSM, 256, P7_SMEM>>>(x, mask, niw, nib);
    tri_mma_kernel<<<dim3(18, 128), 256, TRI_SMEM>>>();
    out2_kernel<<<OGRID, 256, O2_SMEM>>>(now, nob, out);
}

// round 16
// speedup vs baseline: 1.9653x; 1.0859x over previous
#include <cuda_runtime.h>
#include <cuda_bf16.h>
#include <cuda_fp16.h>
#include <math.h>
#include <stdint.h>

#define SDIM 768
#define CCH  128
#define NTOK (SDIM*SDIM)        // 589824 tokens
#define SELEM 75497472          // 128 * 589824
#define NSM   148

// Scratch: a, b, tri, gate all fp16
__device__ __half g_ahi[SELEM];
__device__ __half g_bhi[SELEM];
__device__ __half g_tri16[SELEM];
__device__ __half g_gate16[SELEM];

// Prepped fp16 weights:
// g_wcI: 4 groups x 128 rows x 128 k; group g row 2r = wgi col(64g+r), row 2r+1 = wpi col(64g+r)
__device__ __half g_wcI[4*128*128];
__device__ __half g_wgo16[128*128];   // wgo^T [n][k]
__device__ __half g_wpo16[128*128];   // wpo^T [co][h]

__device__ __forceinline__ float sigmoidf_(float v) {
    return 1.f / (1.f + __expf(-v));
}
__device__ __forceinline__ uint32_t smem_u32(const void* p) {
    uint32_t a;
    asm("{ .reg .u64 t; cvta.to.shared.u64 t, %1; cvt.u32.u64 %0, t; }"
        : "=r"(a) : "l"(p));
    return a;
}
#define CP_ASYNC16(d, s)  asm volatile("cp.async.cg.shared.global [%0], [%1], 16;" :: "r"(d), "l"(s))
#define CP_COMMIT()       asm volatile("cp.async.commit_group;" ::: "memory")
#define CP_WAIT0()        asm volatile("cp.async.wait_group 0;" ::: "memory")
#define CP_WAIT1()        asm volatile("cp.async.wait_group 1;" ::: "memory")

__device__ __forceinline__ void ldsm4(uint32_t* r, uint32_t addr) {
    asm volatile("ldmatrix.sync.aligned.m8n8.x4.shared.b16 {%0,%1,%2,%3}, [%4];"
        : "=r"(r[0]), "=r"(r[1]), "=r"(r[2]), "=r"(r[3]) : "r"(addr));
}
__device__ __forceinline__ void mma16816h(float* d, const uint32_t* a, const uint32_t* b) {
    asm volatile("mma.sync.aligned.m16n8k16.row.col.f32.f16.f16.f32 "
        "{%0,%1,%2,%3}, {%4,%5,%6,%7}, {%8,%9}, {%0,%1,%2,%3};"
        : "+f"(d[0]), "+f"(d[1]), "+f"(d[2]), "+f"(d[3])
        : "r"(a[0]), "r"(a[1]), "r"(a[2]), "r"(a[3]), "r"(b[0]), "r"(b[1]));
}

// ---------------------------------------------------------------------------
// Kernel 0: weight prep.
// ---------------------------------------------------------------------------
__global__ void __launch_bounds__(256) prep_w_kernel(
    const float* __restrict__ wgi, const float* __restrict__ wpi,
    const float* __restrict__ wgo, const float* __restrict__ wpo)
{
    int idx = blockIdx.x*256 + threadIdx.x;   // 0..65535
    {
        int g = idx >> 14, rem = idx & 16383;
        int row = rem >> 7, k = rem & 127;
        int col = g*64 + (row >> 1);
        float v = (row & 1) ? wpi[k*256 + col] : wgi[k*256 + col];
        g_wcI[idx] = __float2half_rn(v);
    }
    if (idx < 16384) {
        int n = idx >> 7, k = idx & 127;
        g_wgo16[idx] = __float2half_rn(wgo[k*128 + n]);
        g_wpo16[idx] = __float2half_rn(wpo[k*128 + n]);
    }
}

// ---------------------------------------------------------------------------
// Kernel 1: proj8 — persistent; 512 threads; 128-token tiles; B resident;
// x prefetched into REGISTERS; A hoisted; direct-store epilogues.
// ---------------------------------------------------------------------------
#define PROW   272
#define PTILE  (128*PROW)         // 34816
#define ATILE  (64*PROW)          // 17408
#define P8_A    0                          // 128 rows x PROW = 34816
#define P8_B    PTILE                      // 34816
#define P8_SMEM (P8_B + 5*PTILE)           // 208896
#define NP8     (NTOK/128)                 // 4608

__global__ void __launch_bounds__(512) proj8_kernel(
    const float* __restrict__ x, const float* __restrict__ mask,
    const float* __restrict__ nw, const float* __restrict__ nb)
{
    extern __shared__ char sm[];
    const uint32_t base = smem_u32(sm);
    const int tid = threadIdx.x;
    const int bid = blockIdx.x;

    const int wid  = tid >> 5;
    const int lane = tid & 31;
    const int m_base = (wid >> 2) * 32;   // 4 m-warps over 128 tokens
    const int n_base = (wid & 3) * 32;    // 4 n-warps
    const int a_row  = lane & 15;
    const int a_half = lane >> 4;
    const int b_quad = lane >> 3;
    const int b_row  = (b_quad >> 1)*8 + (lane & 7);
    const int b_half = b_quad & 1;

    // --- load ALL 5 B chunks once ---
    const __half* csrc[5] = { g_wcI, g_wcI + 16384, g_wcI + 32768,
                              g_wcI + 49152, g_wgo16 };
    for (int cc = 0; cc < 5; cc++) {
        const __half* s = csrc[cc];
        uint32_t dst = base + P8_B + cc*PTILE;
        #pragma unroll
        for (int rep = 0; rep < 4; rep++) {
            int it = tid + rep*512;
            int row = it >> 4, q = it & 15;
            CP_ASYNC16(dst + row*PROW + q*16, (const char*)(s + row*128) + q*16);
        }
    }
    CP_COMMIT();

    const int tl = tid >> 2, qq = tid & 3;    // LN: 4 threads per token, 128 tok

    // --- first x tile into registers ---
    float v[32];
    {
        const float* xrow = x + (size_t)((size_t)bid*128 + tl)*CCH + qq*32;
        #pragma unroll
        for (int i = 0; i < 8; i++) {
            float4 f = __ldg((const float4*)(xrow + i*4));
            v[i*4]=f.x; v[i*4+1]=f.y; v[i*4+2]=f.z; v[i*4+3]=f.w;
        }
    }
    CP_WAIT0();
    __syncthreads();

    for (int tile = bid; tile < NP8; tile += NSM) {
        const int t0 = tile * 128;

        // --- LN from registers -> fp16 A ---
        {
            float s = 0.f;
            #pragma unroll
            for (int i = 0; i < 32; i++) s += v[i];
            s += __shfl_xor_sync(0xFFFFFFFFu, s, 1);
            s += __shfl_xor_sync(0xFFFFFFFFu, s, 2);
            float m = s * (1.f/128.f);
            float q2 = 0.f;
            #pragma unroll
            for (int i = 0; i < 32; i++) { float d = v[i]-m; q2 += d*d; }
            q2 += __shfl_xor_sync(0xFFFFFFFFu, q2, 1);
            q2 += __shfl_xor_sync(0xFFFFFFFFu, q2, 2);
            float rs = rsqrtf(q2 * (1.f/128.f) + 1e-5f);

            #pragma unroll
            for (int i = 0; i < 16; i++) {
                int k = qq*32 + i*2;
                float v0 = (v[i*2]   - m)*rs*__ldg(&nw[k])   + __ldg(&nb[k]);
                float v1 = (v[i*2+1] - m)*rs*__ldg(&nw[k+1]) + __ldg(&nb[k+1]);
                __half2 hh;
                hh.x = __float2half_rn(v0);
                hh.y = __float2half_rn(v1);
                *(__half2*)(sm + P8_A + tl*PROW + k*2) = hh;
            }
        }
        __syncthreads();   // A visible; v registers now dead

        // --- register-prefetch next x tile (overlaps MMA) ---
        if (tile + NSM < NP8) {
            const float* xrow = x + (size_t)((size_t)(tile + NSM)*128 + tl)*CCH + qq*32;
            #pragma unroll
            for (int i = 0; i < 8; i++) {
                float4 f = __ldg((const float4*)(xrow + i*4));
                v[i*4]=f.x; v[i*4+1]=f.y; v[i*4+2]=f.z; v[i*4+3]=f.w;
            }
        }

        // --- hoist A fragments to registers (once per tile) ---
        uint32_t Af[8][2][4];
        #pragma unroll
        for (int ks = 0; ks < 8; ks++) {
            const uint32_t koff = ks*32;
            #pragma unroll
            for (int mt = 0; mt < 2; mt++) {
                uint32_t r = (m_base + mt*16 + a_row)*PROW + koff + a_half*16;
                ldsm4(Af[ks][mt], base + P8_A + r);
            }
        }

        // --- 5 chunks, B resident, A in registers, direct-store epilogues ---
        #pragma unroll
        for (int c = 0; c < 5; c++) {
            const uint32_t sb = base + P8_B + c*PTILE;
            float acc[2][4][4];
            #pragma unroll
            for (int mt = 0; mt < 2; mt++)
                #pragma unroll
                for (int nt = 0; nt < 4; nt++)
                    #pragma unroll
                    for (int r = 0; r < 4; r++) acc[mt][nt][r] = 0.f;

            #pragma unroll
            for (int ks = 0; ks < 8; ks++) {
                const uint32_t koff = ks*32;
                uint32_t Bf[4][2];
                #pragma unroll
                for (int p = 0; p < 2; p++) {
                    uint32_t r = (n_base + p*16 + b_row)*PROW + koff + b_half*16;
                    uint32_t th[4];
                    ldsm4(th, sb + r);
                    Bf[2*p][0]   = th[0]; Bf[2*p][1]   = th[1];
                    Bf[2*p+1][0] = th[2]; Bf[2*p+1][1] = th[3];
                }
                #pragma unroll
                for (int mt = 0; mt < 2; mt++)
                    #pragma unroll
                    for (int nt = 0; nt < 4; nt++)
                        mma16816h(acc[mt][nt], Af[ks][mt], Bf[nt]);
            }

            if (c < 4) {
                // a/b epilogue: direct scalar-half stores, channel-major
                const bool isA = (c < 2);
                const int cgl = (c & 1) * 64;
                __half* dst = isA ? g_ahi : g_bhi;
                #pragma unroll
                for (int mt = 0; mt < 2; mt++) {
                    #pragma unroll
                    for (int rp = 0; rp < 2; rp++) {
                        int t = t0 + m_base + mt*16 + rp*8 + (lane >> 2);
                        float mk = isA ? __ldg(&mask[t]) : 1.f;
                        #pragma unroll
                        for (int nt = 0; nt < 4; nt++) {
                            int cch = cgl + (n_base >> 1) + nt*4 + (lane & 3);
                            float val = sigmoidf_(acc[mt][nt][rp*2]) * acc[mt][nt][rp*2+1] * mk;
                            dst[(size_t)cch*NTOK + t] = __float2half_rn(val);
                        }
                    }
                }
            } else {
                // out-gate epilogue: token-major sigmoid -> fp16
                #pragma unroll
                for (int mt = 0; mt < 2; mt++) {
                    #pragma unroll
                    for (int rp = 0; rp < 2; rp++) {
                        int t = t0 + m_base + mt*16 + rp*8 + (lane >> 2);
                        #pragma unroll
                        for (int nt = 0; nt < 4; nt++) {
                            int ch = n_base + nt*8 + (lane & 3)*2;
                            __half2 f;
                            f.x = __float2half_rn(sigmoidf_(acc[mt][nt][rp*2]));
                            f.y = __float2half_rn(sigmoidf_(acc[mt][nt][rp*2+1]));
                            *(__half2*)&g_gate16[(size_t)t*CCH + ch] = f;
                        }
                    }
                }
            }
        }

        __syncthreads();   // all warps done (incl. hoist) before next LN writes A
    }
}

// ---------------------------------------------------------------------------
// Kernel 2: tri2 — 256x128 output tile, K-chunk=128, double-buffered. (R15)
// ---------------------------------------------------------------------------
#define TA_TILE  (256*PROW)          // 69632
#define TB_TILE  (128*PROW)          // 34816
#define TCHUNK   (TA_TILE + TB_TILE) // 104448
#define TRI_SMEM (2*TCHUNK)          // 208896

__device__ __forceinline__ void tri2_load_chunk(
    uint32_t sbuf, const __half* sA, const __half* sB, int kk, int tid)
{
    #pragma unroll
    for (int rep = 0; rep < 16; rep++) {
        int it  = tid + rep*256;
        int row = it >> 4, q = it & 15;
        CP_ASYNC16(sbuf + row*PROW + q*16, sA + (size_t)row*SDIM + kk + q*8);
    }
    #pragma unroll
    for (int rep = 0; rep < 8; rep++) {
        int it  = tid + rep*256;
        int row = it >> 4, q = it & 15;
        CP_ASYNC16(sbuf + TA_TILE + row*PROW + q*16,
                   sB + (size_t)row*SDIM + kk + q*8);
    }
}

__global__ void __launch_bounds__(256) tri_mma_kernel()
{
    extern __shared__ char dynsm[];
    const uint32_t base = smem_u32(dynsm);

    const int tid  = threadIdx.x;
    const int wid  = tid >> 5;
    const int lane = tid & 31;
    const int m_base = (wid >> 1) * 64;
    const int n_base = (wid & 1) * 64;

    const int c  = blockIdx.y;
    const int i0 = (blockIdx.x / 6) * 256;
    const int j0 = (blockIdx.x % 6) * 128;

    const __half* sAh = g_ahi + (size_t)c*NTOK + (size_t)i0*SDIM;
    const __half* sBh = g_bhi + (size_t)c*NTOK + (size_t)j0*SDIM;

    float acc[4][8][4];
    #pragma unroll
    for (int mt = 0; mt < 4; mt++)
        #pragma unroll
        for (int nt = 0; nt < 8; nt++)
            #pragma unroll
            for (int r = 0; r < 4; r++) acc[mt][nt][r] = 0.f;

    const int a_row  = lane & 15;
    const int a_half = lane >> 4;
    const int b_quad = lane >> 3;
    const int b_row  = (b_quad >> 1) * 8 + (lane & 7);
    const int b_half = b_quad & 1;

    tri2_load_chunk(base, sAh, sBh, 0, tid); CP_COMMIT();

    for (int n = 0; n < 6; n++) {
        if (n + 1 < 6) {
            tri2_load_chunk(base + ((n+1)&1)*TCHUNK, sAh, sBh, (n+1)*128, tid);
            CP_COMMIT();
            CP_WAIT1();
        } else {
            CP_WAIT0();
        }
        __syncthreads();

        const uint32_t sb = base + (n&1)*TCHUNK;
        #pragma unroll
        for (int ks = 0; ks < 8; ks++) {
            uint32_t Ah[4][4], Bh[8][2];
            const uint32_t koff = ks*32;
            #pragma unroll
            for (int mt = 0; mt < 4; mt++) {
                uint32_t r = (m_base + mt*16 + a_row)*PROW + koff + a_half*16;
                ldsm4(Ah[mt], sb + r);
            }
            #pragma unroll
            for (int p = 0; p < 4; p++) {
                uint32_t r = (n_base + p*16 + b_row)*PROW + koff + b_half*16;
                uint32_t th[4];
                ldsm4(th, sb + TA_TILE + r);
                Bh[2*p][0]   = th[0]; Bh[2*p][1]   = th[1];
                Bh[2*p+1][0] = th[2]; Bh[2*p+1][1] = th[3];
            }
            #pragma unroll
            for (int mt = 0; mt < 4; mt++)
                #pragma unroll
                for (int nt = 0; nt < 8; nt++)
                    mma16816h(acc[mt][nt], Ah[mt], Bh[nt]);
        }
        __syncthreads();
    }

    __half* T = g_tri16 + (size_t)c*NTOK;
    const int er = i0 + m_base + (lane >> 2);
    const int ec2 = j0 + n_base + (lane & 3)*2;
    #pragma unroll
    for (int mt = 0; mt < 4; mt++) {
        #pragma unroll
        for (int nt = 0; nt < 8; nt++) {
            int rr = er + mt*16;
            int cc = ec2 + nt*8;
            __half2 v0; v0.x = __float2half_rn(acc[mt][nt][0]);
                        v0.y = __float2half_rn(acc[mt][nt][1]);
            __half2 v1; v1.x = __float2half_rn(acc[mt][nt][2]);
                        v1.y = __float2half_rn(acc[mt][nt][3]);
            *(__half2*)&T[(size_t)rr*SDIM + cc]     = v0;
            *(__half2*)&T[(size_t)(rr+8)*SDIM + cc] = v1;
        }
    }
}

// ---------------------------------------------------------------------------
// Kernel 3: out2 — persistent, 256 thr, 64-token tiles, 2 CTAs/SM. (R14 exact)
// ---------------------------------------------------------------------------
#define TROW     144
#define O2_TRI   0
#define O2_A     18432
#define O2_B     (O2_A + ATILE)
#define O2_SMEM  (O2_B + PTILE)         // 70656
#define NOT64    (NTOK/64)
#define OGRID    (2*NSM)

__global__ void __launch_bounds__(256) out2_kernel(
    const float* __restrict__ now, const float* __restrict__ nob,
    float* __restrict__ out)
{
    extern __shared__ char sm[];
    const uint32_t base = smem_u32(sm);
    const int tid = threadIdx.x;
    const int bid = blockIdx.x;

    #pragma unroll
    for (int rep = 0; rep < 8; rep++) {
        int it = tid + rep*256;
        int row = it >> 4, q = it & 15;
        CP_ASYNC16(base + O2_B + row*PROW + q*16,
                   (const char*)(g_wpo16 + row*128) + q*16);
    }
    {
        int t0 = bid * 64;
        #pragma unroll
        for (int rep = 0; rep < 4; rep++) {
            int it = tid + rep*256;
            int ch = it >> 3, q = it & 7;
            CP_ASYNC16(base + O2_TRI + ch*TROW + q*16,
                       g_tri16 + (size_t)ch*NTOK + t0 + q*8);
        }
    }
    CP_COMMIT();

    const int wid  = tid >> 5;
    const int lane = tid & 31;
    const int m_base = (wid >> 2) * 32;
    const int n_base = (wid & 3) * 32;
    const int a_row  = lane & 15;
    const int a_half = lane >> 4;
    const int b_quad = lane >> 3;
    const int b_row  = (b_quad >> 1)*8 + (lane & 7);
    const int b_half = b_quad & 1;
    const int er = m_base + (lane >> 2);
    const int ec = n_base + (lane & 3)*2;

    const __half* trs = (const __half*)(sm + O2_TRI);
    const int tl = tid >> 2, qq = tid & 3;

    for (int tile = bid; tile < NOT64; tile += OGRID) {
        const int t0 = tile * 64;
        CP_WAIT0();
        __syncthreads();

        {
            float s = 0.f;
            float vch[32];
            #pragma unroll
            for (int j = 0; j < 32; j++) {
                vch[j] = __half2float(trs[(qq*32 + j)*72 + tl]);
                s += vch[j];
            }
            s += __shfl_xor_sync(0xFFFFFFFFu, s, 1);
            s += __shfl_xor_sync(0xFFFFFFFFu, s, 2);
            float m = s * (1.f/128.f);
            float q2 = 0.f;
            #pragma unroll
            for (int j = 0; j < 32; j++) {
                float d = vch[j] - m;
                q2 += d*d;
            }
            q2 += __shfl_xor_sync(0xFFFFFFFFu, q2, 1);
            q2 += __shfl_xor_sync(0xFFFFFFFFu, q2, 2);
            float rs = rsqrtf(q2 * (1.f/128.f) + 1e-5f);

            #pragma unroll
            for (int j = 0; j < 16; j++) {
                int ch = qq*32 + j*2;
                float v0 = (vch[j*2]   - m)*rs*__ldg(&now[ch])   + __ldg(&nob[ch]);
                float v1 = (vch[j*2+1] - m)*rs*__ldg(&now[ch+1]) + __ldg(&nob[ch+1]);
                __half2 hh;
                hh.x = __float2half_rn(v0);
                hh.y = __float2half_rn(v1);
                *(__half2*)(sm + O2_A + tl*PROW + ch*2) = hh;
            }
        }
        __syncthreads();

        if (tile + OGRID < NOT64) {
            int nt0 = (tile + OGRID) * 64;
            #pragma unroll
            for (int rep = 0; rep < 4; rep++) {
                int it = tid + rep*256;
                int ch = it >> 3, q = it & 7;
                CP_ASYNC16(base + O2_TRI + ch*TROW + q*16,
                           g_tri16 + (size_t)ch*NTOK + nt0 + q*8);
            }
        }
        CP_COMMIT();

        float acc[2][4][4];
        #pragma unroll
        for (int mt = 0; mt < 2; mt++)
            #pragma unroll
            for (int nt = 0; nt < 4; nt++)
                #pragma unroll
                for (int r = 0; r < 4; r++) acc[mt][nt][r] = 0.f;

        #pragma unroll
        for (int ks = 0; ks < 8; ks++) {
            const uint32_t koff = ks*32;
            uint32_t Ah[2][4];
            #pragma unroll
            for (int mt = 0; mt < 2; mt++) {
                uint32_t r = (m_base + mt*16 + a_row)*PROW + koff + a_half*16;
                ldsm4(Ah[mt], base + O2_A + r);
            }
            uint32_t Bf[4][2];
            #pragma unroll
            for (int p = 0; p < 2; p++) {
                uint32_t r = (n_base + p*16 + b_row)*PROW + koff + b_half*16;
                uint32_t th[4];
                ldsm4(th, base + O2_B + r);
                Bf[2*p][0]   = th[0]; Bf[2*p][1]   = th[1];
                Bf[2*p+1][0] = th[2]; Bf[2*p+1][1] = th[3];
            }
            #pragma unroll
            for (int mt = 0; mt < 2; mt++)
                #pragma unroll
                for (int nt = 0; nt < 4; nt++) mma16816h(acc[mt][nt], Ah[mt], Bf[nt]);
        }

        #pragma unroll
        for (int mt = 0; mt < 2; mt++) {
            #pragma unroll
            for (int rp = 0; rp < 2; rp++) {
                int t = t0 + er + mt*16 + rp*8;
                #pragma unroll
                for (int nt = 0; nt < 4; nt++) {
                    int cc = ec + nt*8;
                    __half2 gh = __ldg((const __half2*)&g_gate16[(size_t)t*CCH + cc]);
                    float2 o = make_float2(acc[mt][nt][rp*2]   * __half2float(gh.x),
                                           acc[mt][nt][rp*2+1] * __half2float(gh.y));
                    *(float2*)&out[(size_t)t*CCH + cc] = o;
                }
            }
        }
        __syncthreads();
    }
}

// ---------------------------------------------------------------------------
extern "C" void kernel_launch(void* const* d_in, const int* in_sizes, int n_in,
                              void* d_out, int out_size)
{
    const float* x    = (const float*)d_in[0];
    const float* mask = (const float*)d_in[1];
    const float* niw  = (const float*)d_in[2];
    const float* nib  = (const float*)d_in[3];
    const float* wgi  = (const float*)d_in[4];
    const float* wpi  = (const float*)d_in[5];
    const float* now  = (const float*)d_in[6];
    const float* nob  = (const float*)d_in[7];
    const float* wgo  = (const float*)d_in[8];
    const float* wpo  = (const float*)d_in[9];
    float* out = (float*)d_out;

    cudaFuncSetAttribute(proj8_kernel,
        cudaFuncAttributeMaxDynamicSharedMemorySize, P8_SMEM);
    cudaFuncSetAttribute(tri_mma_kernel,
        cudaFuncAttributeMaxDynamicSharedMemorySize, TRI_SMEM);
    cudaFuncSetAttribute(out2_kernel,
        cudaFuncAttributeMaxDynamicSharedMemorySize, O2_SMEM);

    prep_w_kernel<<<256, 256>>>(wgi, wpi, wgo, wpo);
    proj8_kernel<<<NSM, 512, P8_SMEM>>>(x, mask, niw, nib);
    tri_mma_kernel<<<dim3(18, 128), 256, TRI_SMEM>>>();
    out2_kernel<<<OGRID, 256, O2_SMEM>>>(now, nob, out);
}